// round 1
// baseline (speedup 1.0000x reference)
#include <cuda_runtime.h>
#include <cstdint>

namespace {
constexpr int DM     = 1024;
constexpr int SEQ    = 2048;
constexpr int NBATCH = 2;
constexpr int TOK    = SEQ * NBATCH;   // 4096
constexpr int NVOCAB = 32000;
}

// ---- scratch (device globals: allocation-free) ----
__device__ float g_Q[TOK * DM];
__device__ float g_K[TOK * DM];
__device__ float g_V[TOK * DM];
__device__ float g_O[TOK * DM];
__device__ float g_S[NBATCH * SEQ * SEQ];   // causal-masked scores

__device__ __forceinline__ uint32_t f2tf(float x) {
    uint32_t u;
    asm("cvt.rna.tf32.f32 %0, %1;" : "=r"(u) : "f"(x));
    return u;
}

__device__ __forceinline__ void mma8(float* c, const uint32_t* a, const uint32_t* b) {
    asm volatile(
        "mma.sync.aligned.m16n8k8.row.col.f32.tf32.tf32.f32 "
        "{%0,%1,%2,%3}, {%4,%5,%6,%7}, {%8,%9}, {%0,%1,%2,%3};\n"
        : "+f"(c[0]), "+f"(c[1]), "+f"(c[2]), "+f"(c[3])
        : "r"(a[0]), "r"(a[1]), "r"(a[2]), "r"(a[3]), "r"(b[0]), "r"(b[1]));
}

// C[M,N] = op(A) @ op(B) with:
//   A: [M,K] row-major (K contiguous). GATHER: row m comes from A[gidx[bm+m]].
//   B: NT (!BNN): [N,K] row-major (K contiguous)  — "B transposed" GEMM
//      NN ( BNN): [K,N] row-major (N contiguous)
// EPI: 0 = +bias then elu(x)+1, 1 = +bias, 2 = causal mask (zero col>row), 3 = none
// TRIK: limit K-loop to bm+128 (A is causal lower-triangular in its K dim)
template<int EPI, bool GATHER, bool BNN, bool TRIK>
__global__ void __launch_bounds__(256)
gemm_tf32(const float* __restrict__ A, const float* __restrict__ B,
          float* __restrict__ C, const float* __restrict__ bias,
          const int* __restrict__ gidx,
          int M, int N, int K,
          long long Az, long long Bz, long long Cz)
{
    A += blockIdx.z * Az;
    B += blockIdx.z * Bz;
    C += blockIdx.z * Cz;

    const int bm   = blockIdx.x * 128;
    const int bn   = blockIdx.y * 128;
    const int tid  = threadIdx.x;
    const int lane = tid & 31;
    const int warp = tid >> 5;
    const int wm   = (warp >> 2) * 64;   // 2 warp-rows
    const int wn   = (warp & 3) * 32;    // 4 warp-cols

    __shared__ uint32_t As[16][132];
    __shared__ uint32_t Bs[16][132];

    float acc[4][4][4];
    #pragma unroll
    for (int i = 0; i < 4; i++)
        #pragma unroll
        for (int j = 0; j < 4; j++)
            #pragma unroll
            for (int r = 0; r < 4; r++) acc[i][j][r] = 0.f;

    const bool fullskip = (EPI == 2) && (bn > bm + 127);

    if (!fullskip) {
        // ---- per-thread global load coords ----
        const float* aPtr[2];
        int aRow[2], aKq[2];
        #pragma unroll
        for (int i = 0; i < 2; i++) {
            int idx = tid + i * 256;          // 512 float4 per A tile
            aRow[i] = idx >> 2;               // 0..127
            aKq[i]  = idx & 3;                // k-quad
            int srcRow = GATHER ? gidx[bm + aRow[i]] : (bm + aRow[i]);
            aPtr[i] = A + (size_t)srcRow * K + aKq[i] * 4;
        }
        const float* bPtr[2];
        int bR[2], bQ[2];
        #pragma unroll
        for (int i = 0; i < 2; i++) {
            int idx = tid + i * 256;
            if (BNN) {
                bR[i] = idx >> 5;             // k row 0..15
                bQ[i] = idx & 31;             // n-quad
                bPtr[i] = B + (size_t)bR[i] * N + bn + bQ[i] * 4;
            } else {
                bR[i] = idx >> 2;             // n row 0..127
                bQ[i] = idx & 3;              // k-quad
                bPtr[i] = B + (size_t)(bn + bR[i]) * K + bQ[i] * 4;
            }
        }

        int nkt = K / 16;
        if (TRIK) { int kl = bm + 128; if (kl < K) nkt = kl / 16; }

        float4 aReg[2], bReg[2];
        #pragma unroll
        for (int i = 0; i < 2; i++) {
            aReg[i] = *(const float4*)(aPtr[i]);
            bReg[i] = *(const float4*)(bPtr[i]);
        }

        // stage registers -> smem (with rna tf32 conversion)
        auto stageStore = [&]() {
            #pragma unroll
            for (int i = 0; i < 2; i++) {
                float va[4] = {aReg[i].x, aReg[i].y, aReg[i].z, aReg[i].w};
                #pragma unroll
                for (int j = 0; j < 4; j++) As[aKq[i] * 4 + j][aRow[i]] = f2tf(va[j]);
                float vb[4] = {bReg[i].x, bReg[i].y, bReg[i].z, bReg[i].w};
                if (BNN) {
                    uint4 pk;
                    pk.x = f2tf(vb[0]); pk.y = f2tf(vb[1]);
                    pk.z = f2tf(vb[2]); pk.w = f2tf(vb[3]);
                    *(uint4*)&Bs[bR[i]][bQ[i] * 4] = pk;
                } else {
                    #pragma unroll
                    for (int j = 0; j < 4; j++) Bs[bQ[i] * 4 + j][bR[i]] = f2tf(vb[j]);
                }
            }
        };

        stageStore();
        __syncthreads();

        for (int kt = 0; kt < nkt; kt++) {
            if (kt + 1 < nkt) {
                #pragma unroll
                for (int i = 0; i < 2; i++) {
                    aReg[i] = *(const float4*)(aPtr[i] + (size_t)(kt + 1) * 16);
                    bReg[i] = BNN ? *(const float4*)(bPtr[i] + (size_t)(kt + 1) * 16 * N)
                                  : *(const float4*)(bPtr[i] + (size_t)(kt + 1) * 16);
                }
            }
            // compute current smem tile: 2 k-steps of 8
            #pragma unroll
            for (int ks = 0; ks < 16; ks += 8) {
                const int kr = ks + (lane & 3);
                const int rr = lane >> 2;
                uint32_t af[4][4];
                #pragma unroll
                for (int mt = 0; mt < 4; mt++) {
                    int mb = wm + mt * 16 + rr;
                    af[mt][0] = As[kr][mb];
                    af[mt][1] = As[kr][mb + 8];
                    af[mt][2] = As[kr + 4][mb];
                    af[mt][3] = As[kr + 4][mb + 8];
                }
                uint32_t bf[4][2];
                #pragma unroll
                for (int nt = 0; nt < 4; nt++) {
                    int nb = wn + nt * 8 + rr;
                    bf[nt][0] = Bs[kr][nb];
                    bf[nt][1] = Bs[kr + 4][nb];
                }
                #pragma unroll
                for (int mt = 0; mt < 4; mt++)
                    #pragma unroll
                    for (int nt = 0; nt < 4; nt++)
                        mma8(acc[mt][nt], af[mt], bf[nt]);
            }
            __syncthreads();
            if (kt + 1 < nkt) {
                stageStore();
                __syncthreads();
            }
        }
    }

    // ---- epilogue ----
    #pragma unroll
    for (int mt = 0; mt < 4; mt++) {
        #pragma unroll
        for (int nt = 0; nt < 4; nt++) {
            int r = bm + wm + mt * 16 + (lane >> 2);
            int c = bn + wn + nt * 8 + ((lane & 3) << 1);
            float v[4] = {acc[mt][nt][0], acc[mt][nt][1], acc[mt][nt][2], acc[mt][nt][3]};
            if (EPI == 0 || EPI == 1) {
                float b0 = bias[c], b1 = bias[c + 1];
                v[0] += b0; v[1] += b1; v[2] += b0; v[3] += b1;
                if (EPI == 0) {
                    #pragma unroll
                    for (int j = 0; j < 4; j++)
                        v[j] = (v[j] > 0.f) ? (v[j] + 1.f) : expf(v[j]);
                }
            } else if (EPI == 2) {
                if (c     > r)     v[0] = 0.f;
                if (c + 1 > r)     v[1] = 0.f;
                if (c     > r + 8) v[2] = 0.f;
                if (c + 1 > r + 8) v[3] = 0.f;
            }
            *(float2*)&C[(size_t)r * N + c]       = make_float2(v[0], v[1]);
            *(float2*)&C[(size_t)(r + 8) * N + c] = make_float2(v[2], v[3]);
        }
    }
}

extern "C" void kernel_launch(void* const* d_in, const int* in_sizes, int n_in,
                              void* d_out, int out_size)
{
    (void)in_sizes; (void)n_in; (void)out_size;
    const int*   x   = (const int*)  d_in[0];
    const float* emb = (const float*)d_in[1];
    const float* wq  = (const float*)d_in[2];
    const float* bq  = (const float*)d_in[3];
    const float* wk  = (const float*)d_in[4];
    const float* bk  = (const float*)d_in[5];
    const float* wv  = (const float*)d_in[6];
    const float* bv  = (const float*)d_in[7];
    const float* wo  = (const float*)d_in[8];
    const float* bo  = (const float*)d_in[9];
    float* out = (float*)d_out;

    float *Qs, *Ks, *Vs, *Os, *Ss;
    cudaGetSymbolAddress((void**)&Qs, g_Q);
    cudaGetSymbolAddress((void**)&Ks, g_K);
    cudaGetSymbolAddress((void**)&Vs, g_V);
    cudaGetSymbolAddress((void**)&Os, g_O);
    cudaGetSymbolAddress((void**)&Ss, g_S);

    dim3 thr(256);

    // 1) fused embed-gather + projections: [4096,1024] = emb[x] @ W^T + b
    dim3 gQKV(TOK / 128, DM / 128, 1);
    gemm_tf32<0, true, false, false><<<gQKV, thr>>>(emb, wq, Qs, bq, x, TOK, DM, DM, 0, 0, 0);
    gemm_tf32<0, true, false, false><<<gQKV, thr>>>(emb, wk, Ks, bk, x, TOK, DM, DM, 0, 0, 0);
    gemm_tf32<1, true, false, false><<<gQKV, thr>>>(emb, wv, Vs, bv, x, TOK, DM, DM, 0, 0, 0);

    // 2) causal scores per batch: S_b = tril(Q_b @ K_b^T)
    dim3 gSc(SEQ / 128, SEQ / 128, NBATCH);
    gemm_tf32<2, false, false, false><<<gSc, thr>>>(
        Qs, Ks, Ss, nullptr, nullptr, SEQ, SEQ, DM,
        (long long)SEQ * DM, (long long)SEQ * DM, (long long)SEQ * SEQ);

    // 3) O_b = S_b @ V_b  (B is [K,N] row-major; K-loop truncated by causality)
    dim3 gAV(SEQ / 128, DM / 128, NBATCH);
    gemm_tf32<3, false, true, true><<<gAV, thr>>>(
        Ss, Vs, Os, nullptr, nullptr, SEQ, DM, SEQ,
        (long long)SEQ * SEQ, (long long)SEQ * DM, (long long)SEQ * DM);

    // 4) logits: [4096,32000] = O @ wo^T + bo  (dominant GEMM)
    dim3 gLg(TOK / 128, NVOCAB / 128, 1);
    gemm_tf32<1, false, false, false><<<gLg, thr>>>(
        Os, wo, out, bo, nullptr, TOK, NVOCAB, DM, 0, 0, 0);
}

// round 3
// speedup vs baseline: 1.2836x; 1.2836x over previous
#include <cuda_runtime.h>
#include <cstdint>

namespace {
constexpr int DM     = 1024;
constexpr int SEQ    = 2048;
constexpr int NBATCH = 2;
constexpr int TOK    = SEQ * NBATCH;   // 4096
constexpr int NVOCAB = 32000;
}

// ---- scratch (device globals: allocation-free) ----
__device__ float g_Q[TOK * DM];
__device__ float g_K[TOK * DM];
__device__ float g_V[TOK * DM];
__device__ float g_O[TOK * DM];
__device__ float g_S[NBATCH * SEQ * SEQ];   // causal-masked scores
__device__ float g_W[NVOCAB * DM];          // rna-rounded wo

__device__ __forceinline__ uint32_t f2tf(float x) {
    uint32_t u;
    asm("cvt.rna.tf32.f32 %0, %1;" : "=r"(u) : "f"(x));
    return u;
}

__device__ __forceinline__ uint32_t smem_u32(const void* p) {
    uint32_t a;
    asm("{ .reg .u64 t; cvta.to.shared.u64 t, %1; cvt.u32.u64 %0, t; }" : "=r"(a) : "l"(p));
    return a;
}

__device__ __forceinline__ void mma8(float* c, const uint32_t* a, const uint32_t* b) {
    asm volatile(
        "mma.sync.aligned.m16n8k8.row.col.f32.tf32.tf32.f32 "
        "{%0,%1,%2,%3}, {%4,%5,%6,%7}, {%8,%9}, {%0,%1,%2,%3};\n"
        : "+f"(c[0]), "+f"(c[1]), "+f"(c[2]), "+f"(c[3])
        : "r"(a[0]), "r"(a[1]), "r"(a[2]), "r"(a[3]), "r"(b[0]), "r"(b[1]));
}

__device__ __forceinline__ void ldsm4(uint32_t* r, uint32_t addr) {
    asm volatile("ldmatrix.sync.aligned.m8n8.x4.shared.b16 {%0,%1,%2,%3}, [%4];"
        : "=r"(r[0]), "=r"(r[1]), "=r"(r[2]), "=r"(r[3]) : "r"(addr));
}

__device__ __forceinline__ void cp16(uint32_t smem, const void* g) {
    asm volatile("cp.async.cg.shared.global [%0], [%1], 16;" :: "r"(smem), "l"(g) : "memory");
}

// ============================================================================
// Fast logits GEMM (legacy tensor path, cp.async + ldmatrix):
//   C[4096,32000] = A[4096,1024] @ B[32000,1024]^T + bias
// Block tile 128x256, warp tile 64x64 (8 warps), 4-stage cp.async, K-chunk 16.
// A and B must already be tf32(rna)-rounded.
// ============================================================================
namespace lg {
constexpr int PITCH     = 80;                       // smem row pitch bytes (16-float row + pad)
constexpr int A_BYTES   = 128 * PITCH;              // 10240
constexpr int B_BYTES   = 256 * PITCH;              // 20480
constexpr int STG_BYTES = A_BYTES + B_BYTES;        // 30720
constexpr int NSTG      = 4;
constexpr int NK        = DM / 16;                  // 64 chunks
constexpr int SMEM_TOT  = NSTG * STG_BYTES;         // 122880
}

__global__ void __launch_bounds__(256, 1)
logits_fast(const float* __restrict__ A, const float* __restrict__ B,
            const float* __restrict__ bias, float* __restrict__ C)
{
    extern __shared__ char smem[];
    const uint32_t sb = smem_u32(smem);
    const int tid  = threadIdx.x;
    const int lane = tid & 31;
    const int warp = tid >> 5;
    const int wm   = (warp >> 2) * 64;   // 2 warp rows
    const int wn   = (warp & 3) * 64;    // 4 warp cols
    const int bm   = blockIdx.x * 128;
    const int bn   = blockIdx.y * 256;

    const int g = lane >> 3;
    const uint32_t aOff = (uint32_t)(((lane & 7) + (g & 1) * 8) * lg::PITCH + (g >> 1) * 16);
    const uint32_t bOff = (uint32_t)(((lane & 7) + (g >> 1) * 8) * lg::PITCH + (g & 1) * 16);

    float acc[4][8][4];
    #pragma unroll
    for (int mt = 0; mt < 4; mt++)
        #pragma unroll
        for (int nt = 0; nt < 8; nt++)
            #pragma unroll
            for (int r = 0; r < 4; r++) acc[mt][nt][r] = 0.f;

    const float* Ag = A + (size_t)bm * DM;
    const float* Bg = B + (size_t)bn * DM;

    auto load_stage = [&](int st) {
        const uint32_t base = sb + (st & 3) * lg::STG_BYTES;
        const int kb = st * 16;
        #pragma unroll
        for (int i = 0; i < 2; i++) {               // A: 512 16B chunks
            int idx = tid + i * 256;
            int row = idx >> 2, kq = idx & 3;
            cp16(base + row * lg::PITCH + kq * 16, Ag + (size_t)row * DM + kb + kq * 4);
        }
        const uint32_t bb = base + lg::A_BYTES;
        #pragma unroll
        for (int i = 0; i < 4; i++) {               // B: 1024 16B chunks
            int idx = tid + i * 256;
            int row = idx >> 2, kq = idx & 3;
            cp16(bb + row * lg::PITCH + kq * 16, Bg + (size_t)row * DM + kb + kq * 4);
        }
        asm volatile("cp.async.commit_group;" ::: "memory");
    };

    load_stage(0); load_stage(1); load_stage(2);

    for (int ck = 0; ck < lg::NK; ck++) {
        asm volatile("cp.async.wait_group 2;" ::: "memory");
        __syncthreads();
        if (ck + 3 < lg::NK) load_stage(ck + 3);

        const uint32_t sa  = sb + (ck & 3) * lg::STG_BYTES;
        const uint32_t sbb = sa + lg::A_BYTES;
        #pragma unroll
        for (int ks = 0; ks < 16; ks += 8) {
            uint32_t af[4][4], bf[8][2];
            #pragma unroll
            for (int mt = 0; mt < 4; mt++)
                ldsm4(af[mt], sa + (wm + mt * 16) * lg::PITCH + ks * 4 + aOff);
            #pragma unroll
            for (int p = 0; p < 4; p++) {
                uint32_t t4[4];
                ldsm4(t4, sbb + (wn + p * 16) * lg::PITCH + ks * 4 + bOff);
                bf[2 * p][0]     = t4[0]; bf[2 * p][1]     = t4[1];
                bf[2 * p + 1][0] = t4[2]; bf[2 * p + 1][1] = t4[3];
            }
            #pragma unroll
            for (int mt = 0; mt < 4; mt++)
                #pragma unroll
                for (int nt = 0; nt < 8; nt++)
                    mma8(acc[mt][nt], af[mt], bf[nt]);
        }
    }

    // ---- epilogue: regs -> smem (per 128-col half) -> coalesced float4 stores ----
    float* buf = (float*)smem;                     // [128][136]
    const int whalf = (warp & 3) >> 1;             // which half this warp's cols live in
    for (int h = 0; h < 2; h++) {
        __syncthreads();
        if (whalf == h) {
            const int cb = wn - h * 128;
            #pragma unroll
            for (int mt = 0; mt < 4; mt++) {
                #pragma unroll
                for (int nt = 0; nt < 8; nt++) {
                    int rr = wm + mt * 16 + (lane >> 2);
                    int cc = cb + nt * 8 + ((lane & 3) << 1);
                    *(float2*)&buf[rr * 136 + cc]       = make_float2(acc[mt][nt][0], acc[mt][nt][1]);
                    *(float2*)&buf[(rr + 8) * 136 + cc] = make_float2(acc[mt][nt][2], acc[mt][nt][3]);
                }
            }
        }
        __syncthreads();
        #pragma unroll
        for (int it = 0; it < 16; it++) {
            int i  = tid + it * 256;
            int rr = i >> 5;
            int c  = (i & 31) * 4;
            const float* sr = buf + rr * 136 + c;
            const float4 bv = *(const float4*)(bias + bn + h * 128 + c);
            float4 v;
            v.x = sr[0] + bv.x; v.y = sr[1] + bv.y;
            v.z = sr[2] + bv.z; v.w = sr[3] + bv.w;
            *(float4*)&C[(size_t)(bm + rr) * NVOCAB + bn + h * 128 + c] = v;
        }
    }
}

// ============================================================================
// wo pre-round: rna tf32 rounding into g_W
// ============================================================================
__global__ void __launch_bounds__(256)
round_wo(const float* __restrict__ in, float* __restrict__ out)
{
    size_t i = ((size_t)blockIdx.x * 256 + threadIdx.x) * 4;
    float4 v = *(const float4*)(in + i);
    uint4 u;
    u.x = f2tf(v.x); u.y = f2tf(v.y); u.z = f2tf(v.z); u.w = f2tf(v.w);
    *(uint4*)(out + i) = u;
}

// ============================================================================
// legacy tf32 mma.sync GEMM (small GEMMs: QKV / scores / AV)
// ============================================================================
// EPI: 0 = +bias then elu(x)+1, 1 = +bias, 2 = causal mask, 3 = rna-tf32-rounded store
template<int EPI, bool GATHER, bool BNN, bool TRIK>
__global__ void __launch_bounds__(256)
gemm_tf32(const float* __restrict__ A, const float* __restrict__ B,
          float* __restrict__ C, const float* __restrict__ bias,
          const int* __restrict__ gidx,
          int M, int N, int K,
          long long Az, long long Bz, long long Cz)
{
    A += blockIdx.z * Az;
    B += blockIdx.z * Bz;
    C += blockIdx.z * Cz;

    const int bm   = blockIdx.x * 128;
    const int bn   = blockIdx.y * 128;
    const int tid  = threadIdx.x;
    const int lane = tid & 31;
    const int warp = tid >> 5;
    const int wm   = (warp >> 2) * 64;
    const int wn   = (warp & 3) * 32;

    __shared__ uint32_t As[16][132];
    __shared__ uint32_t Bs[16][132];

    float acc[4][4][4];
    #pragma unroll
    for (int i = 0; i < 4; i++)
        #pragma unroll
        for (int j = 0; j < 4; j++)
            #pragma unroll
            for (int r = 0; r < 4; r++) acc[i][j][r] = 0.f;

    const bool fullskip = (EPI == 2) && (bn > bm + 127);

    if (!fullskip) {
        const float* aPtr[2];
        int aRow[2], aKq[2];
        #pragma unroll
        for (int i = 0; i < 2; i++) {
            int idx = tid + i * 256;
            aRow[i] = idx >> 2;
            aKq[i]  = idx & 3;
            int srcRow = GATHER ? gidx[bm + aRow[i]] : (bm + aRow[i]);
            aPtr[i] = A + (size_t)srcRow * K + aKq[i] * 4;
        }
        const float* bPtr[2];
        int bR[2], bQ[2];
        #pragma unroll
        for (int i = 0; i < 2; i++) {
            int idx = tid + i * 256;
            if (BNN) {
                bR[i] = idx >> 5;
                bQ[i] = idx & 31;
                bPtr[i] = B + (size_t)bR[i] * N + bn + bQ[i] * 4;
            } else {
                bR[i] = idx >> 2;
                bQ[i] = idx & 3;
                bPtr[i] = B + (size_t)(bn + bR[i]) * K + bQ[i] * 4;
            }
        }

        int nkt = K / 16;
        if (TRIK) { int kl = bm + 128; if (kl < K) nkt = kl / 16; }

        float4 aReg[2], bReg[2];
        #pragma unroll
        for (int i = 0; i < 2; i++) {
            aReg[i] = *(const float4*)(aPtr[i]);
            bReg[i] = *(const float4*)(bPtr[i]);
        }

        auto stageStore = [&]() {
            #pragma unroll
            for (int i = 0; i < 2; i++) {
                float va[4] = {aReg[i].x, aReg[i].y, aReg[i].z, aReg[i].w};
                #pragma unroll
                for (int j = 0; j < 4; j++) As[aKq[i] * 4 + j][aRow[i]] = f2tf(va[j]);
                float vb[4] = {bReg[i].x, bReg[i].y, bReg[i].z, bReg[i].w};
                if (BNN) {
                    uint4 pk;
                    pk.x = f2tf(vb[0]); pk.y = f2tf(vb[1]);
                    pk.z = f2tf(vb[2]); pk.w = f2tf(vb[3]);
                    *(uint4*)&Bs[bR[i]][bQ[i] * 4] = pk;
                } else {
                    #pragma unroll
                    for (int j = 0; j < 4; j++) Bs[bQ[i] * 4 + j][bR[i]] = f2tf(vb[j]);
                }
            }
        };

        stageStore();
        __syncthreads();

        for (int kt = 0; kt < nkt; kt++) {
            if (kt + 1 < nkt) {
                #pragma unroll
                for (int i = 0; i < 2; i++) {
                    aReg[i] = *(const float4*)(aPtr[i] + (size_t)(kt + 1) * 16);
                    bReg[i] = BNN ? *(const float4*)(bPtr[i] + (size_t)(kt + 1) * 16 * N)
                                  : *(const float4*)(bPtr[i] + (size_t)(kt + 1) * 16);
                }
            }
            #pragma unroll
            for (int ks = 0; ks < 16; ks += 8) {
                const int kr = ks + (lane & 3);
                const int rr = lane >> 2;
                uint32_t af[4][4];
                #pragma unroll
                for (int mt = 0; mt < 4; mt++) {
                    int mb = wm + mt * 16 + rr;
                    af[mt][0] = As[kr][mb];
                    af[mt][1] = As[kr][mb + 8];
                    af[mt][2] = As[kr + 4][mb];
                    af[mt][3] = As[kr + 4][mb + 8];
                }
                uint32_t bf[4][2];
                #pragma unroll
                for (int nt = 0; nt < 4; nt++) {
                    int nb = wn + nt * 8 + rr;
                    bf[nt][0] = Bs[kr][nb];
                    bf[nt][1] = Bs[kr + 4][nb];
                }
                #pragma unroll
                for (int mt = 0; mt < 4; mt++)
                    #pragma unroll
                    for (int nt = 0; nt < 4; nt++)
                        mma8(acc[mt][nt], af[mt], bf[nt]);
            }
            __syncthreads();
            if (kt + 1 < nkt) {
                stageStore();
                __syncthreads();
            }
        }
    }

    #pragma unroll
    for (int mt = 0; mt < 4; mt++) {
        #pragma unroll
        for (int nt = 0; nt < 4; nt++) {
            int r = bm + wm + mt * 16 + (lane >> 2);
            int c = bn + wn + nt * 8 + ((lane & 3) << 1);
            float v[4] = {acc[mt][nt][0], acc[mt][nt][1], acc[mt][nt][2], acc[mt][nt][3]};
            if (EPI == 0 || EPI == 1) {
                float b0 = bias[c], b1 = bias[c + 1];
                v[0] += b0; v[1] += b1; v[2] += b0; v[3] += b1;
                if (EPI == 0) {
                    #pragma unroll
                    for (int j = 0; j < 4; j++)
                        v[j] = (v[j] > 0.f) ? (v[j] + 1.f) : expf(v[j]);
                }
            } else if (EPI == 2) {
                if (c     > r)     v[0] = 0.f;
                if (c + 1 > r)     v[1] = 0.f;
                if (c     > r + 8) v[2] = 0.f;
                if (c + 1 > r + 8) v[3] = 0.f;
            } else if (EPI == 3) {
                #pragma unroll
                for (int j = 0; j < 4; j++) v[j] = __uint_as_float(f2tf(v[j]));
            }
            *(float2*)&C[(size_t)r * N + c]       = make_float2(v[0], v[1]);
            *(float2*)&C[(size_t)(r + 8) * N + c] = make_float2(v[2], v[3]);
        }
    }
}

extern "C" void kernel_launch(void* const* d_in, const int* in_sizes, int n_in,
                              void* d_out, int out_size)
{
    (void)in_sizes; (void)n_in; (void)out_size;
    const int*   x   = (const int*)  d_in[0];
    const float* emb = (const float*)d_in[1];
    const float* wq  = (const float*)d_in[2];
    const float* bq  = (const float*)d_in[3];
    const float* wk  = (const float*)d_in[4];
    const float* bk  = (const float*)d_in[5];
    const float* wv  = (const float*)d_in[6];
    const float* bv  = (const float*)d_in[7];
    const float* wo  = (const float*)d_in[8];
    const float* bo  = (const float*)d_in[9];
    float* out = (float*)d_out;

    float *Qs, *Ks, *Vs, *Os, *Ss, *Ws;
    cudaGetSymbolAddress((void**)&Qs, g_Q);
    cudaGetSymbolAddress((void**)&Ks, g_K);
    cudaGetSymbolAddress((void**)&Vs, g_V);
    cudaGetSymbolAddress((void**)&Os, g_O);
    cudaGetSymbolAddress((void**)&Ss, g_S);
    cudaGetSymbolAddress((void**)&Ws, g_W);

    cudaFuncSetAttribute(logits_fast,
                         cudaFuncAttributeMaxDynamicSharedMemorySize, lg::SMEM_TOT);

    dim3 thr(256);

    // 0) rna-round wo into g_W (mma truncates; pre-rounding keeps accuracy)
    round_wo<<<NVOCAB * DM / (256 * 4), thr>>>(wo, Ws);

    // 1) fused embed-gather + projections
    dim3 gQKV(TOK / 128, DM / 128, 1);
    gemm_tf32<0, true, false, false><<<gQKV, thr>>>(emb, wq, Qs, bq, x, TOK, DM, DM, 0, 0, 0);
    gemm_tf32<0, true, false, false><<<gQKV, thr>>>(emb, wk, Ks, bk, x, TOK, DM, DM, 0, 0, 0);
    gemm_tf32<1, true, false, false><<<gQKV, thr>>>(emb, wv, Vs, bv, x, TOK, DM, DM, 0, 0, 0);

    // 2) causal scores per batch
    dim3 gSc(SEQ / 128, SEQ / 128, NBATCH);
    gemm_tf32<2, false, false, false><<<gSc, thr>>>(
        Qs, Ks, Ss, nullptr, nullptr, SEQ, SEQ, DM,
        (long long)SEQ * DM, (long long)SEQ * DM, (long long)SEQ * SEQ);

    // 3) O_b = S_b @ V_b (stores rna-rounded so logits mma truncation is harmless)
    dim3 gAV(SEQ / 128, DM / 128, NBATCH);
    gemm_tf32<3, false, true, true><<<gAV, thr>>>(
        Ss, Vs, Os, nullptr, nullptr, SEQ, DM, SEQ,
        (long long)SEQ * SEQ, (long long)SEQ * DM, (long long)SEQ * DM);

    // 4) logits: [4096,32000] = O @ g_W^T + bo  (cp.async + ldmatrix kernel)
    dim3 gLg(TOK / 128, NVOCAB / 256, 1);
    logits_fast<<<gLg, thr, lg::SMEM_TOT>>>(Os, Ws, bo, out);
}

// round 6
// speedup vs baseline: 1.9110x; 1.4888x over previous
#include <cuda_runtime.h>
#include <cuda_fp16.h>
#include <cstdint>

namespace {
constexpr int DM     = 1024;
constexpr int SEQ    = 2048;
constexpr int NBATCH = 2;
constexpr int TOK    = SEQ * NBATCH;   // 4096
constexpr int NVOCAB = 32000;
constexpr float O_SCALE     = 512.f;        // O stored as O/512 in fp16 (exact pow2)
constexpr float O_SCALE_INV = 1.f / 512.f;
}

// ---- scratch (device globals: allocation-free) ----
__device__ float  g_Q[TOK * DM];
__device__ float  g_K[TOK * DM];
__device__ float  g_V[TOK * DM];
__device__ float  g_S[NBATCH * SEQ * SEQ];   // causal-masked scores
__device__ __half g_Oh[TOK * DM];            // fp16 attention output (scaled by 1/512)
__device__ __half g_Wh[NVOCAB * DM];         // fp16 wo

__device__ __forceinline__ uint32_t f2tf(float x) {
    uint32_t u;
    asm("cvt.rna.tf32.f32 %0, %1;" : "=r"(u) : "f"(x));
    return u;
}

__device__ __forceinline__ uint32_t smem_u32(const void* p) {
    uint32_t a;
    asm("{ .reg .u64 t; cvta.to.shared.u64 t, %1; cvt.u32.u64 %0, t; }" : "=r"(a) : "l"(p));
    return a;
}

__device__ __forceinline__ void mma8(float* c, const uint32_t* a, const uint32_t* b) {
    asm volatile(
        "mma.sync.aligned.m16n8k8.row.col.f32.tf32.tf32.f32 "
        "{%0,%1,%2,%3}, {%4,%5,%6,%7}, {%8,%9}, {%0,%1,%2,%3};\n"
        : "+f"(c[0]), "+f"(c[1]), "+f"(c[2]), "+f"(c[3])
        : "r"(a[0]), "r"(a[1]), "r"(a[2]), "r"(a[3]), "r"(b[0]), "r"(b[1]));
}

__device__ __forceinline__ void mma16h(float* c, const uint32_t* a, const uint32_t* b) {
    asm volatile(
        "mma.sync.aligned.m16n8k16.row.col.f32.f16.f16.f32 "
        "{%0,%1,%2,%3}, {%4,%5,%6,%7}, {%8,%9}, {%0,%1,%2,%3};\n"
        : "+f"(c[0]), "+f"(c[1]), "+f"(c[2]), "+f"(c[3])
        : "r"(a[0]), "r"(a[1]), "r"(a[2]), "r"(a[3]), "r"(b[0]), "r"(b[1]));
}

__device__ __forceinline__ void ldsm4(uint32_t* r, uint32_t addr) {
    asm volatile("ldmatrix.sync.aligned.m8n8.x4.shared.b16 {%0,%1,%2,%3}, [%4];"
        : "=r"(r[0]), "=r"(r[1]), "=r"(r[2]), "=r"(r[3]) : "r"(addr));
}

__device__ __forceinline__ void cp16(uint32_t smem, const void* g) {
    asm volatile("cp.async.cg.shared.global [%0], [%1], 16;" :: "r"(smem), "l"(g) : "memory");
}

// ============================================================================
// fp16 logits GEMM: C[4096,32000] = (A/512)h @ Bh^T * 512 + bias
// Block tile 128x256, warp tile 64x64 (8 warps), 4-stage cp.async, K-chunk 32.
// ============================================================================
namespace lh {
constexpr int PITCH     = 80;                 // 64B data (32 fp16) + 16B pad
constexpr int A_BYTES   = 128 * PITCH;        // 10240
constexpr int B_BYTES   = 256 * PITCH;        // 20480
constexpr int STG_BYTES = A_BYTES + B_BYTES;  // 30720
constexpr int NK        = DM / 32;            // 32 chunks
constexpr int SMEM_TOT  = 4 * STG_BYTES;      // 122880
}

__global__ void __launch_bounds__(256, 1)
logits_fp16(const __half* __restrict__ A, const __half* __restrict__ B,
            const float* __restrict__ bias, float* __restrict__ C)
{
    extern __shared__ char smem[];
    const uint32_t sb = smem_u32(smem);
    const int tid  = threadIdx.x;
    const int lane = tid & 31;
    const int warp = tid >> 5;
    const int wm   = (warp >> 2) * 64;   // 2 warp rows
    const int wn   = (warp & 3) * 64;    // 4 warp cols
    const int bm   = blockIdx.x * 128;
    const int bn   = blockIdx.y * 256;

    const int g = lane >> 3;
    const uint32_t frOff = (uint32_t)(((lane & 7) + (g & 1) * 8) * lh::PITCH + (g >> 1) * 16);

    float acc[4][8][4];
    #pragma unroll
    for (int mt = 0; mt < 4; mt++)
        #pragma unroll
        for (int nt = 0; nt < 8; nt++)
            #pragma unroll
            for (int r = 0; r < 4; r++) acc[mt][nt][r] = 0.f;

    const __half* Ag = A + (size_t)bm * DM;
    const __half* Bg = B + (size_t)bn * DM;

    auto load_stage = [&](int st) {
        const uint32_t base = sb + (st & 3) * lh::STG_BYTES;
        const int kb = st * 32;
        #pragma unroll
        for (int i = 0; i < 2; i++) {               // A: 128 rows x 4 16B chunks
            int idx = tid + i * 256;
            int row = idx >> 2, kq = idx & 3;
            cp16(base + row * lh::PITCH + kq * 16, Ag + (size_t)row * DM + kb + kq * 8);
        }
        const uint32_t bb = base + lh::A_BYTES;
        #pragma unroll
        for (int i = 0; i < 4; i++) {               // B: 256 rows x 4 16B chunks
            int idx = tid + i * 256;
            int row = idx >> 2, kq = idx & 3;
            cp16(bb + row * lh::PITCH + kq * 16, Bg + (size_t)row * DM + kb + kq * 8);
        }
        asm volatile("cp.async.commit_group;" ::: "memory");
    };

    load_stage(0); load_stage(1); load_stage(2);

    for (int ck = 0; ck < lh::NK; ck++) {
        asm volatile("cp.async.wait_group 2;" ::: "memory");
        __syncthreads();
        if (ck + 3 < lh::NK) load_stage(ck + 3);

        const uint32_t sa  = sb + (ck & 3) * lh::STG_BYTES;
        const uint32_t sbb = sa + lh::A_BYTES;
        #pragma unroll
        for (int ks = 0; ks < 2; ks++) {            // two k16 steps per chunk
            uint32_t af[4][4], bf[8][2];
            #pragma unroll
            for (int mt = 0; mt < 4; mt++)
                ldsm4(af[mt], sa + (wm + mt * 16) * lh::PITCH + ks * 32 + frOff);
            #pragma unroll
            for (int p = 0; p < 4; p++) {
                uint32_t t4[4];
                ldsm4(t4, sbb + (wn + p * 16) * lh::PITCH + ks * 32 + frOff);
                bf[2 * p][0]     = t4[0]; bf[2 * p][1]     = t4[2];
                bf[2 * p + 1][0] = t4[1]; bf[2 * p + 1][1] = t4[3];
            }
            #pragma unroll
            for (int mt = 0; mt < 4; mt++)
                #pragma unroll
                for (int nt = 0; nt < 8; nt++)
                    mma16h(acc[mt][nt], af[mt], bf[nt]);
        }
    }

    // ---- epilogue: regs -> smem (per 128-col half) -> coalesced float4 stores ----
    float* buf = (float*)smem;                     // [128][136]
    const int whalf = (warp & 3) >> 1;
    for (int h = 0; h < 2; h++) {
        __syncthreads();
        if (whalf == h) {
            const int cb = wn - h * 128;
            #pragma unroll
            for (int mt = 0; mt < 4; mt++) {
                #pragma unroll
                for (int nt = 0; nt < 8; nt++) {
                    int rr = wm + mt * 16 + (lane >> 2);
                    int cc = cb + nt * 8 + ((lane & 3) << 1);
                    *(float2*)&buf[rr * 136 + cc]       = make_float2(acc[mt][nt][0], acc[mt][nt][1]);
                    *(float2*)&buf[(rr + 8) * 136 + cc] = make_float2(acc[mt][nt][2], acc[mt][nt][3]);
                }
            }
        }
        __syncthreads();
        #pragma unroll
        for (int it = 0; it < 16; it++) {
            int i  = tid + it * 256;
            int rr = i >> 5;
            int c  = (i & 31) * 4;
            const float* sr = buf + rr * 136 + c;
            const float4 bv = *(const float4*)(bias + bn + h * 128 + c);
            float4 v;
            v.x = sr[0] * O_SCALE + bv.x;
            v.y = sr[1] * O_SCALE + bv.y;
            v.z = sr[2] * O_SCALE + bv.z;
            v.w = sr[3] * O_SCALE + bv.w;
            *(float4*)&C[(size_t)(bm + rr) * NVOCAB + bn + h * 128 + c] = v;
        }
    }
}

// ============================================================================
// wo -> fp16 conversion (8 elems/thread)
// ============================================================================
__global__ void __launch_bounds__(256)
cvt_wo_half(const float* __restrict__ in, __half* __restrict__ out)
{
    size_t i = ((size_t)blockIdx.x * 256 + threadIdx.x) * 8;
    float4 v0 = *(const float4*)(in + i);
    float4 v1 = *(const float4*)(in + i + 4);
    __half2 h[4];
    h[0] = __floats2half2_rn(v0.x, v0.y);
    h[1] = __floats2half2_rn(v0.z, v0.w);
    h[2] = __floats2half2_rn(v1.x, v1.y);
    h[3] = __floats2half2_rn(v1.z, v1.w);
    *(uint4*)(out + i) = *(uint4*)h;
}

// ============================================================================
// legacy tf32 mma.sync GEMM (small GEMMs: QKV / scores / AV)
// EPI: 0 = +bias elu+1, 1 = +bias, 2 = causal mask, 4 = fp16 store scaled by 1/512
// NOTE (EPI==4): C points to a __half array; the blockIdx.z offset Cz must be
// applied in HALF units, so it is NOT applied to the float* at the top.
// ============================================================================
template<int EPI, bool GATHER, bool BNN, bool TRIK>
__global__ void __launch_bounds__(256)
gemm_tf32(const float* __restrict__ A, const float* __restrict__ B,
          float* __restrict__ C, const float* __restrict__ bias,
          const int* __restrict__ gidx,
          int M, int N, int K,
          long long Az, long long Bz, long long Cz)
{
    A += blockIdx.z * Az;
    B += blockIdx.z * Bz;
    if (EPI != 4) C += blockIdx.z * Cz;

    const int bm   = blockIdx.x * 128;
    const int bn   = blockIdx.y * 128;
    const int tid  = threadIdx.x;
    const int lane = tid & 31;
    const int warp = tid >> 5;
    const int wm   = (warp >> 2) * 64;
    const int wn   = (warp & 3) * 32;

    __shared__ uint32_t As[16][132];
    __shared__ uint32_t Bs[16][132];

    float acc[4][4][4];
    #pragma unroll
    for (int i = 0; i < 4; i++)
        #pragma unroll
        for (int j = 0; j < 4; j++)
            #pragma unroll
            for (int r = 0; r < 4; r++) acc[i][j][r] = 0.f;

    const bool fullskip = (EPI == 2) && (bn > bm + 127);

    if (!fullskip) {
        const float* aPtr[2];
        int aRow[2], aKq[2];
        #pragma unroll
        for (int i = 0; i < 2; i++) {
            int idx = tid + i * 256;
            aRow[i] = idx >> 2;
            aKq[i]  = idx & 3;
            int srcRow = GATHER ? gidx[bm + aRow[i]] : (bm + aRow[i]);
            aPtr[i] = A + (size_t)srcRow * K + aKq[i] * 4;
        }
        const float* bPtr[2];
        int bR[2], bQ[2];
        #pragma unroll
        for (int i = 0; i < 2; i++) {
            int idx = tid + i * 256;
            if (BNN) {
                bR[i] = idx >> 5;
                bQ[i] = idx & 31;
                bPtr[i] = B + (size_t)bR[i] * N + bn + bQ[i] * 4;
            } else {
                bR[i] = idx >> 2;
                bQ[i] = idx & 3;
                bPtr[i] = B + (size_t)(bn + bR[i]) * K + bQ[i] * 4;
            }
        }

        int nkt = K / 16;
        if (TRIK) { int kl = bm + 128; if (kl < K) nkt = kl / 16; }

        float4 aReg[2], bReg[2];
        #pragma unroll
        for (int i = 0; i < 2; i++) {
            aReg[i] = *(const float4*)(aPtr[i]);
            bReg[i] = *(const float4*)(bPtr[i]);
        }

        auto stageStore = [&]() {
            #pragma unroll
            for (int i = 0; i < 2; i++) {
                float va[4] = {aReg[i].x, aReg[i].y, aReg[i].z, aReg[i].w};
                #pragma unroll
                for (int j = 0; j < 4; j++) As[aKq[i] * 4 + j][aRow[i]] = f2tf(va[j]);
                float vb[4] = {bReg[i].x, bReg[i].y, bReg[i].z, bReg[i].w};
                if (BNN) {
                    uint4 pk;
                    pk.x = f2tf(vb[0]); pk.y = f2tf(vb[1]);
                    pk.z = f2tf(vb[2]); pk.w = f2tf(vb[3]);
                    *(uint4*)&Bs[bR[i]][bQ[i] * 4] = pk;
                } else {
                    #pragma unroll
                    for (int j = 0; j < 4; j++) Bs[bQ[i] * 4 + j][bR[i]] = f2tf(vb[j]);
                }
            }
        };

        stageStore();
        __syncthreads();

        for (int kt = 0; kt < nkt; kt++) {
            if (kt + 1 < nkt) {
                #pragma unroll
                for (int i = 0; i < 2; i++) {
                    aReg[i] = *(const float4*)(aPtr[i] + (size_t)(kt + 1) * 16);
                    bReg[i] = BNN ? *(const float4*)(bPtr[i] + (size_t)(kt + 1) * 16 * N)
                                  : *(const float4*)(bPtr[i] + (size_t)(kt + 1) * 16);
                }
            }
            #pragma unroll
            for (int ks = 0; ks < 16; ks += 8) {
                const int kr = ks + (lane & 3);
                const int rr = lane >> 2;
                uint32_t af[4][4];
                #pragma unroll
                for (int mt = 0; mt < 4; mt++) {
                    int mb = wm + mt * 16 + rr;
                    af[mt][0] = As[kr][mb];
                    af[mt][1] = As[kr][mb + 8];
                    af[mt][2] = As[kr + 4][mb];
                    af[mt][3] = As[kr + 4][mb + 8];
                }
                uint32_t bf[4][2];
                #pragma unroll
                for (int nt = 0; nt < 4; nt++) {
                    int nb = wn + nt * 8 + rr;
                    bf[nt][0] = Bs[kr][nb];
                    bf[nt][1] = Bs[kr + 4][nb];
                }
                #pragma unroll
                for (int mt = 0; mt < 4; mt++)
                    #pragma unroll
                    for (int nt = 0; nt < 4; nt++)
                        mma8(acc[mt][nt], af[mt], bf[nt]);
            }
            __syncthreads();
            if (kt + 1 < nkt) {
                stageStore();
                __syncthreads();
            }
        }
    }

    __half* Ch = nullptr;
    if (EPI == 4) Ch = (__half*)C + (size_t)blockIdx.z * Cz;   // z-offset in HALF units

    #pragma unroll
    for (int mt = 0; mt < 4; mt++) {
        #pragma unroll
        for (int nt = 0; nt < 4; nt++) {
            int r = bm + wm + mt * 16 + (lane >> 2);
            int c = bn + wn + nt * 8 + ((lane & 3) << 1);
            float v[4] = {acc[mt][nt][0], acc[mt][nt][1], acc[mt][nt][2], acc[mt][nt][3]};
            if (EPI == 0 || EPI == 1) {
                float b0 = bias[c], b1 = bias[c + 1];
                v[0] += b0; v[1] += b1; v[2] += b0; v[3] += b1;
                if (EPI == 0) {
                    #pragma unroll
                    for (int j = 0; j < 4; j++)
                        v[j] = (v[j] > 0.f) ? (v[j] + 1.f) : expf(v[j]);
                }
            } else if (EPI == 2) {
                if (c     > r)     v[0] = 0.f;
                if (c + 1 > r)     v[1] = 0.f;
                if (c     > r + 8) v[2] = 0.f;
                if (c + 1 > r + 8) v[3] = 0.f;
            }
            if (EPI == 4) {
                *(__half2*)&Ch[(size_t)r * N + c] =
                    __floats2half2_rn(v[0] * O_SCALE_INV, v[1] * O_SCALE_INV);
                *(__half2*)&Ch[(size_t)(r + 8) * N + c] =
                    __floats2half2_rn(v[2] * O_SCALE_INV, v[3] * O_SCALE_INV);
            } else {
                *(float2*)&C[(size_t)r * N + c]       = make_float2(v[0], v[1]);
                *(float2*)&C[(size_t)(r + 8) * N + c] = make_float2(v[2], v[3]);
            }
        }
    }
}

extern "C" void kernel_launch(void* const* d_in, const int* in_sizes, int n_in,
                              void* d_out, int out_size)
{
    (void)in_sizes; (void)n_in; (void)out_size;
    const int*   x   = (const int*)  d_in[0];
    const float* emb = (const float*)d_in[1];
    const float* wq  = (const float*)d_in[2];
    const float* bq  = (const float*)d_in[3];
    const float* wk  = (const float*)d_in[4];
    const float* bk  = (const float*)d_in[5];
    const float* wv  = (const float*)d_in[6];
    const float* bv  = (const float*)d_in[7];
    const float* wo  = (const float*)d_in[8];
    const float* bo  = (const float*)d_in[9];
    float* out = (float*)d_out;

    float *Qs, *Ks, *Vs, *Ss;
    __half *Oh, *Wh;
    cudaGetSymbolAddress((void**)&Qs, g_Q);
    cudaGetSymbolAddress((void**)&Ks, g_K);
    cudaGetSymbolAddress((void**)&Vs, g_V);
    cudaGetSymbolAddress((void**)&Ss, g_S);
    cudaGetSymbolAddress((void**)&Oh, g_Oh);
    cudaGetSymbolAddress((void**)&Wh, g_Wh);

    cudaFuncSetAttribute(logits_fp16,
                         cudaFuncAttributeMaxDynamicSharedMemorySize, lh::SMEM_TOT);

    dim3 thr(256);

    // 0) wo -> fp16
    cvt_wo_half<<<NVOCAB * DM / (256 * 8), thr>>>(wo, Wh);

    // 1) fused embed-gather + projections
    dim3 gQKV(TOK / 128, DM / 128, 1);
    gemm_tf32<0, true, false, false><<<gQKV, thr>>>(emb, wq, Qs, bq, x, TOK, DM, DM, 0, 0, 0);
    gemm_tf32<0, true, false, false><<<gQKV, thr>>>(emb, wk, Ks, bk, x, TOK, DM, DM, 0, 0, 0);
    gemm_tf32<1, true, false, false><<<gQKV, thr>>>(emb, wv, Vs, bv, x, TOK, DM, DM, 0, 0, 0);

    // 2) causal scores per batch
    dim3 gSc(SEQ / 128, SEQ / 128, NBATCH);
    gemm_tf32<2, false, false, false><<<gSc, thr>>>(
        Qs, Ks, Ss, nullptr, nullptr, SEQ, SEQ, DM,
        (long long)SEQ * DM, (long long)SEQ * DM, (long long)SEQ * SEQ);

    // 3) O_b = S_b @ V_b, output as fp16 scaled by 1/512 (fp16-range safety)
    dim3 gAV(SEQ / 128, DM / 128, NBATCH);
    gemm_tf32<4, false, true, true><<<gAV, thr>>>(
        Ss, Vs, (float*)Oh, nullptr, nullptr, SEQ, DM, SEQ,
        (long long)SEQ * SEQ, (long long)SEQ * DM, (long long)SEQ * DM);

    // 4) logits: [4096,32000] = (Oh @ Wh^T) * 512 + bo  (fp16 mma)
    dim3 gLg(TOK / 128, NVOCAB / 256, 1);
    logits_fp16<<<gLg, thr, lh::SMEM_TOT>>>(Oh, Wh, bo, out);
}

// round 7
// speedup vs baseline: 2.4164x; 1.2645x over previous
#include <cuda_runtime.h>
#include <cuda_fp16.h>
#include <cstdint>

namespace {
constexpr int DM     = 1024;
constexpr int SEQ    = 2048;
constexpr int NBATCH = 2;
constexpr int TOK    = SEQ * NBATCH;   // 4096
constexpr int NVOCAB = 32000;
constexpr float O_SCALE     = 512.f;   // O stored as O/512 in fp16 (exact pow2)
constexpr float O_SCALE_INV = 1.f / 512.f;
}

// ---- scratch (device globals: allocation-free) ----
__device__ __half g_eh[TOK * DM];            // gathered embeddings, fp16
__device__ __half g_Qh[TOK * DM];
__device__ __half g_Kh[TOK * DM];
__device__ __half g_Vt[DM * TOK];            // V transposed: Vt[d][b*SEQ+t]
__device__ __half g_Sh[NBATCH * SEQ * SEQ];  // causal scores, fp16
__device__ __half g_Oh[TOK * DM];            // attention out / 512, fp16
__device__ __half g_Wh[NVOCAB * DM];         // fp16 wo
__device__ __half g_Wq[DM * DM];
__device__ __half g_Wk[DM * DM];
__device__ __half g_Wv[DM * DM];

__device__ __forceinline__ uint32_t smem_u32(const void* p) {
    uint32_t a;
    asm("{ .reg .u64 t; cvta.to.shared.u64 t, %1; cvt.u32.u64 %0, t; }" : "=r"(a) : "l"(p));
    return a;
}

__device__ __forceinline__ void mma16h(float* c, const uint32_t* a, const uint32_t* b) {
    asm volatile(
        "mma.sync.aligned.m16n8k16.row.col.f32.f16.f16.f32 "
        "{%0,%1,%2,%3}, {%4,%5,%6,%7}, {%8,%9}, {%0,%1,%2,%3};\n"
        : "+f"(c[0]), "+f"(c[1]), "+f"(c[2]), "+f"(c[3])
        : "r"(a[0]), "r"(a[1]), "r"(a[2]), "r"(a[3]), "r"(b[0]), "r"(b[1]));
}

__device__ __forceinline__ void ldsm4(uint32_t* r, uint32_t addr) {
    asm volatile("ldmatrix.sync.aligned.m8n8.x4.shared.b16 {%0,%1,%2,%3}, [%4];"
        : "=r"(r[0]), "=r"(r[1]), "=r"(r[2]), "=r"(r[3]) : "r"(addr));
}

__device__ __forceinline__ void cp16(uint32_t smem, const void* g) {
    asm volatile("cp.async.cg.shared.global [%0], [%1], 16;" :: "r"(smem), "l"(g) : "memory");
}

// ---- shared tile constants (128x256 CTA tile, K-chunk 32, 4 stages) ----
namespace lh {
constexpr int PITCH     = 80;                 // 64B data (32 fp16) + 16B pad
constexpr int A_BYTES   = 128 * PITCH;        // 10240
constexpr int B_BYTES   = 256 * PITCH;        // 20480
constexpr int STG_BYTES = A_BYTES + B_BYTES;  // 30720
constexpr int SMEM_TOT  = 4 * STG_BYTES;      // 122880
}

// ============================================================================
// Unified fp16 NT GEMM: C[gridM*128, gridN*256] = A @ B^T (+ epilogue), fp16 out
// A: [M, lda] row-major fp16 (K contiguous).  B: [N, ldb] row-major fp16.
// EPI: 0 = +colbias then elu+1, 1 = +colbias, 2 = causal mask (zero col>row),
//      5 = +rowbias, 6 = scale by 1/512.
// TRIK: truncate K loop to bm+128 (A lower-triangular in K dim).
// Az/Bz/Cz: per-blockIdx.z offsets in ELEMENTS (half units).
// ============================================================================
template<int EPI, bool TRIK>
__global__ void __launch_bounds__(256, 1)
gemm_h(const __half* __restrict__ A, int lda,
       const __half* __restrict__ B, int ldb,
       const float* __restrict__ bias,
       __half* __restrict__ C, int ldc,
       int K, long long Az, long long Bz, long long Cz)
{
    A += (size_t)blockIdx.z * Az;
    B += (size_t)blockIdx.z * Bz;
    C += (size_t)blockIdx.z * Cz;

    const int bm = blockIdx.x * 128;
    const int bn = blockIdx.y * 256;
    if (EPI == 2 && bn > bm + 127) return;   // fully-masked tile: never read later

    extern __shared__ char smem[];
    const uint32_t sb = smem_u32(smem);
    const int tid  = threadIdx.x;
    const int lane = tid & 31;
    const int warp = tid >> 5;
    const int wm   = (warp >> 2) * 64;
    const int wn   = (warp & 3) * 64;

    const int g = lane >> 3;
    const uint32_t frOff = (uint32_t)(((lane & 7) + (g & 1) * 8) * lh::PITCH + (g >> 1) * 16);

    float acc[4][8][4];
    #pragma unroll
    for (int mt = 0; mt < 4; mt++)
        #pragma unroll
        for (int nt = 0; nt < 8; nt++)
            #pragma unroll
            for (int r = 0; r < 4; r++) acc[mt][nt][r] = 0.f;

    const __half* Ag = A + (size_t)bm * lda;
    const __half* Bg = B + (size_t)bn * ldb;

    int nk = K / 32;
    if (TRIK) { int kl = bm + 128; if (kl < K) nk = kl / 32; }

    auto load_stage = [&](int st) {
        const uint32_t base = sb + (st & 3) * lh::STG_BYTES;
        const int kb = st * 32;
        #pragma unroll
        for (int i = 0; i < 2; i++) {               // A: 128 rows x 4 16B chunks
            int idx = tid + i * 256;
            int row = idx >> 2, kq = idx & 3;
            cp16(base + row * lh::PITCH + kq * 16, Ag + (size_t)row * lda + kb + kq * 8);
        }
        const uint32_t bb = base + lh::A_BYTES;
        #pragma unroll
        for (int i = 0; i < 4; i++) {               // B: 256 rows x 4 16B chunks
            int idx = tid + i * 256;
            int row = idx >> 2, kq = idx & 3;
            cp16(bb + row * lh::PITCH + kq * 16, Bg + (size_t)row * ldb + kb + kq * 8);
        }
        asm volatile("cp.async.commit_group;" ::: "memory");
    };

    load_stage(0); load_stage(1); load_stage(2);

    for (int ck = 0; ck < nk; ck++) {
        asm volatile("cp.async.wait_group 2;" ::: "memory");
        __syncthreads();
        if (ck + 3 < nk) load_stage(ck + 3);

        const uint32_t sa  = sb + (ck & 3) * lh::STG_BYTES;
        const uint32_t sbb = sa + lh::A_BYTES;
        #pragma unroll
        for (int ks = 0; ks < 2; ks++) {
            uint32_t af[4][4], bf[8][2];
            #pragma unroll
            for (int mt = 0; mt < 4; mt++)
                ldsm4(af[mt], sa + (wm + mt * 16) * lh::PITCH + ks * 32 + frOff);
            #pragma unroll
            for (int p = 0; p < 4; p++) {
                uint32_t t4[4];
                ldsm4(t4, sbb + (wn + p * 16) * lh::PITCH + ks * 32 + frOff);
                bf[2 * p][0]     = t4[0]; bf[2 * p][1]     = t4[2];
                bf[2 * p + 1][0] = t4[1]; bf[2 * p + 1][1] = t4[3];
            }
            #pragma unroll
            for (int mt = 0; mt < 4; mt++)
                #pragma unroll
                for (int nt = 0; nt < 8; nt++)
                    mma16h(acc[mt][nt], af[mt], bf[nt]);
        }
    }

    // ---- epilogue: direct fp16 fragment stores ----
    #pragma unroll
    for (int mt = 0; mt < 4; mt++) {
        #pragma unroll
        for (int nt = 0; nt < 8; nt++) {
            int r = bm + wm + mt * 16 + (lane >> 2);
            int c = bn + wn + nt * 8 + ((lane & 3) << 1);
            float v[4] = {acc[mt][nt][0], acc[mt][nt][1], acc[mt][nt][2], acc[mt][nt][3]};
            if (EPI == 0 || EPI == 1) {
                float b0 = bias[c], b1 = bias[c + 1];
                v[0] += b0; v[1] += b1; v[2] += b0; v[3] += b1;
                if (EPI == 0) {
                    #pragma unroll
                    for (int j = 0; j < 4; j++)
                        v[j] = (v[j] > 0.f) ? (v[j] + 1.f) : expf(v[j]);
                }
            } else if (EPI == 5) {
                float b0 = bias[r], b1 = bias[r + 8];
                v[0] += b0; v[1] += b0; v[2] += b1; v[3] += b1;
            } else if (EPI == 2) {
                if (c     > r)     v[0] = 0.f;
                if (c + 1 > r)     v[1] = 0.f;
                if (c     > r + 8) v[2] = 0.f;
                if (c + 1 > r + 8) v[3] = 0.f;
            } else if (EPI == 6) {
                #pragma unroll
                for (int j = 0; j < 4; j++) v[j] *= O_SCALE_INV;
            }
            *(__half2*)&C[(size_t)r * ldc + c]       = __floats2half2_rn(v[0], v[1]);
            *(__half2*)&C[(size_t)(r + 8) * ldc + c] = __floats2half2_rn(v[2], v[3]);
        }
    }
}

// ============================================================================
// fp16 logits GEMM: C[4096,32000] = (A/512)h @ Bh^T * 512 + bias  (fp32 out)
// ============================================================================
__global__ void __launch_bounds__(256, 1)
logits_fp16(const __half* __restrict__ A, const __half* __restrict__ B,
            const float* __restrict__ bias, float* __restrict__ C)
{
    extern __shared__ char smem[];
    const uint32_t sb = smem_u32(smem);
    const int tid  = threadIdx.x;
    const int lane = tid & 31;
    const int warp = tid >> 5;
    const int wm   = (warp >> 2) * 64;
    const int wn   = (warp & 3) * 64;
    const int bm   = blockIdx.x * 128;
    const int bn   = blockIdx.y * 256;

    const int g = lane >> 3;
    const uint32_t frOff = (uint32_t)(((lane & 7) + (g & 1) * 8) * lh::PITCH + (g >> 1) * 16);

    float acc[4][8][4];
    #pragma unroll
    for (int mt = 0; mt < 4; mt++)
        #pragma unroll
        for (int nt = 0; nt < 8; nt++)
            #pragma unroll
            for (int r = 0; r < 4; r++) acc[mt][nt][r] = 0.f;

    const __half* Ag = A + (size_t)bm * DM;
    const __half* Bg = B + (size_t)bn * DM;

    auto load_stage = [&](int st) {
        const uint32_t base = sb + (st & 3) * lh::STG_BYTES;
        const int kb = st * 32;
        #pragma unroll
        for (int i = 0; i < 2; i++) {
            int idx = tid + i * 256;
            int row = idx >> 2, kq = idx & 3;
            cp16(base + row * lh::PITCH + kq * 16, Ag + (size_t)row * DM + kb + kq * 8);
        }
        const uint32_t bb = base + lh::A_BYTES;
        #pragma unroll
        for (int i = 0; i < 4; i++) {
            int idx = tid + i * 256;
            int row = idx >> 2, kq = idx & 3;
            cp16(bb + row * lh::PITCH + kq * 16, Bg + (size_t)row * DM + kb + kq * 8);
        }
        asm volatile("cp.async.commit_group;" ::: "memory");
    };

    load_stage(0); load_stage(1); load_stage(2);

    const int NK = DM / 32;
    for (int ck = 0; ck < NK; ck++) {
        asm volatile("cp.async.wait_group 2;" ::: "memory");
        __syncthreads();
        if (ck + 3 < NK) load_stage(ck + 3);

        const uint32_t sa  = sb + (ck & 3) * lh::STG_BYTES;
        const uint32_t sbb = sa + lh::A_BYTES;
        #pragma unroll
        for (int ks = 0; ks < 2; ks++) {
            uint32_t af[4][4], bf[8][2];
            #pragma unroll
            for (int mt = 0; mt < 4; mt++)
                ldsm4(af[mt], sa + (wm + mt * 16) * lh::PITCH + ks * 32 + frOff);
            #pragma unroll
            for (int p = 0; p < 4; p++) {
                uint32_t t4[4];
                ldsm4(t4, sbb + (wn + p * 16) * lh::PITCH + ks * 32 + frOff);
                bf[2 * p][0]     = t4[0]; bf[2 * p][1]     = t4[2];
                bf[2 * p + 1][0] = t4[1]; bf[2 * p + 1][1] = t4[3];
            }
            #pragma unroll
            for (int mt = 0; mt < 4; mt++)
                #pragma unroll
                for (int nt = 0; nt < 8; nt++)
                    mma16h(acc[mt][nt], af[mt], bf[nt]);
        }
    }

    // ---- epilogue: regs -> smem (per 128-col half) -> coalesced float4 stores ----
    float* buf = (float*)smem;                     // [128][136]
    const int whalf = (warp & 3) >> 1;
    for (int h = 0; h < 2; h++) {
        __syncthreads();
        if (whalf == h) {
            const int cb = wn - h * 128;
            #pragma unroll
            for (int mt = 0; mt < 4; mt++) {
                #pragma unroll
                for (int nt = 0; nt < 8; nt++) {
                    int rr = wm + mt * 16 + (lane >> 2);
                    int cc = cb + nt * 8 + ((lane & 3) << 1);
                    *(float2*)&buf[rr * 136 + cc]       = make_float2(acc[mt][nt][0], acc[mt][nt][1]);
                    *(float2*)&buf[(rr + 8) * 136 + cc] = make_float2(acc[mt][nt][2], acc[mt][nt][3]);
                }
            }
        }
        __syncthreads();
        #pragma unroll
        for (int it = 0; it < 16; it++) {
            int i  = tid + it * 256;
            int rr = i >> 5;
            int c  = (i & 31) * 4;
            const float* sr = buf + rr * 136 + c;
            const float4 bv = *(const float4*)(bias + bn + h * 128 + c);
            float4 v;
            v.x = sr[0] * O_SCALE + bv.x;
            v.y = sr[1] * O_SCALE + bv.y;
            v.z = sr[2] * O_SCALE + bv.z;
            v.w = sr[3] * O_SCALE + bv.w;
            *(float4*)&C[(size_t)(bm + rr) * NVOCAB + bn + h * 128 + c] = v;
        }
    }
}

// ============================================================================
// conversion / gather kernels
// ============================================================================
__global__ void __launch_bounds__(256)
cvt_f2h(const float* __restrict__ in, __half* __restrict__ out)
{
    size_t i = ((size_t)blockIdx.x * 256 + threadIdx.x) * 8;
    float4 v0 = *(const float4*)(in + i);
    float4 v1 = *(const float4*)(in + i + 4);
    __half2 h[4];
    h[0] = __floats2half2_rn(v0.x, v0.y);
    h[1] = __floats2half2_rn(v0.z, v0.w);
    h[2] = __floats2half2_rn(v1.x, v1.y);
    h[3] = __floats2half2_rn(v1.z, v1.w);
    *(uint4*)(out + i) = *(uint4*)h;
}

__global__ void __launch_bounds__(256)
gather_cvt(const int* __restrict__ x, const float* __restrict__ emb,
           __half* __restrict__ out)
{
    const int t = blockIdx.x;
    const int d = threadIdx.x * 4;
    const float4 v = *(const float4*)(emb + (size_t)x[t] * DM + d);
    __half2 h0 = __floats2half2_rn(v.x, v.y);
    __half2 h1 = __floats2half2_rn(v.z, v.w);
    uint2 u;
    u.x = *(uint32_t*)&h0;
    u.y = *(uint32_t*)&h1;
    *(uint2*)(out + (size_t)t * DM + d) = u;
}

extern "C" void kernel_launch(void* const* d_in, const int* in_sizes, int n_in,
                              void* d_out, int out_size)
{
    (void)in_sizes; (void)n_in; (void)out_size;
    const int*   x   = (const int*)  d_in[0];
    const float* emb = (const float*)d_in[1];
    const float* wq  = (const float*)d_in[2];
    const float* bq  = (const float*)d_in[3];
    const float* wk  = (const float*)d_in[4];
    const float* bk  = (const float*)d_in[5];
    const float* wv  = (const float*)d_in[6];
    const float* bv  = (const float*)d_in[7];
    const float* wo  = (const float*)d_in[8];
    const float* bo  = (const float*)d_in[9];
    float* out = (float*)d_out;

    __half *eh, *Qh, *Kh, *Vt, *Sh, *Oh, *Wh, *Wq, *Wk, *Wv;
    cudaGetSymbolAddress((void**)&eh, g_eh);
    cudaGetSymbolAddress((void**)&Qh, g_Qh);
    cudaGetSymbolAddress((void**)&Kh, g_Kh);
    cudaGetSymbolAddress((void**)&Vt, g_Vt);
    cudaGetSymbolAddress((void**)&Sh, g_Sh);
    cudaGetSymbolAddress((void**)&Oh, g_Oh);
    cudaGetSymbolAddress((void**)&Wh, g_Wh);
    cudaGetSymbolAddress((void**)&Wq, g_Wq);
    cudaGetSymbolAddress((void**)&Wk, g_Wk);
    cudaGetSymbolAddress((void**)&Wv, g_Wv);

    cudaFuncSetAttribute(logits_fp16,
                         cudaFuncAttributeMaxDynamicSharedMemorySize, lh::SMEM_TOT);
    cudaFuncSetAttribute(gemm_h<0, false>,
                         cudaFuncAttributeMaxDynamicSharedMemorySize, lh::SMEM_TOT);
    cudaFuncSetAttribute(gemm_h<5, false>,
                         cudaFuncAttributeMaxDynamicSharedMemorySize, lh::SMEM_TOT);
    cudaFuncSetAttribute(gemm_h<2, false>,
                         cudaFuncAttributeMaxDynamicSharedMemorySize, lh::SMEM_TOT);
    cudaFuncSetAttribute(gemm_h<6, true>,
                         cudaFuncAttributeMaxDynamicSharedMemorySize, lh::SMEM_TOT);

    dim3 thr(256);

    // 0) conversions
    cvt_f2h<<<NVOCAB * DM / (256 * 8), thr>>>(wo, Wh);
    cvt_f2h<<<DM * DM / (256 * 8), thr>>>(wq, Wq);
    cvt_f2h<<<DM * DM / (256 * 8), thr>>>(wk, Wk);
    cvt_f2h<<<DM * DM / (256 * 8), thr>>>(wv, Wv);
    gather_cvt<<<TOK, thr>>>(x, emb, eh);

    // 1) Q/K projections: [4096,1024] = e_h @ W^T, elu+1 + bias
    dim3 gQK(TOK / 128, DM / 256, 1);
    gemm_h<0, false><<<gQK, thr, lh::SMEM_TOT>>>(eh, DM, Wq, DM, bq, Qh, DM, DM, 0, 0, 0);
    gemm_h<0, false><<<gQK, thr, lh::SMEM_TOT>>>(eh, DM, Wk, DM, bk, Kh, DM, DM, 0, 0, 0);

    // 2) V pre-transposed: Vt[1024,4096] = wv @ e_h^T + bv (row bias)
    dim3 gVt(DM / 128, TOK / 256, 1);
    gemm_h<5, false><<<gVt, thr, lh::SMEM_TOT>>>(Wv, DM, eh, DM, bv, Vt, TOK, DM, 0, 0, 0);

    // 3) causal scores per batch: S_b = tril(Q_b @ K_b^T), fp16
    dim3 gSc(SEQ / 128, SEQ / 256, NBATCH);
    gemm_h<2, false><<<gSc, thr, lh::SMEM_TOT>>>(
        Qh, DM, Kh, DM, nullptr, Sh, SEQ, DM,
        (long long)SEQ * DM, (long long)SEQ * DM, (long long)SEQ * SEQ);

    // 4) O_b = (S_b @ Vt_b^T) / 512, TRIK-truncated K loop
    dim3 gAV(SEQ / 128, DM / 256, NBATCH);
    gemm_h<6, true><<<gAV, thr, lh::SMEM_TOT>>>(
        Sh, SEQ, Vt, TOK, nullptr, Oh, DM, SEQ,
        (long long)SEQ * SEQ, (long long)SEQ, (long long)SEQ * DM);

    // 5) logits: [4096,32000] = (Oh @ Wh^T) * 512 + bo
    dim3 gLg(TOK / 128, NVOCAB / 256, 1);
    logits_fp16<<<gLg, thr, lh::SMEM_TOT>>>(Oh, Wh, bo, out);
}

// round 8
// speedup vs baseline: 2.6916x; 1.1139x over previous
#include <cuda_runtime.h>
#include <cuda_fp16.h>
#include <cstdint>

namespace {
constexpr int DM     = 1024;
constexpr int SEQ    = 2048;
constexpr int NBATCH = 2;
constexpr int TOK    = SEQ * NBATCH;   // 4096
constexpr int NVOCAB = 32000;
constexpr float O_SCALE     = 512.f;   // O stored as O/512 in fp16 (exact pow2)
constexpr float O_SCALE_INV = 1.f / 512.f;
}

// ---- scratch (device globals: allocation-free) ----
__device__ __half g_eh[TOK * DM];              // gathered embeddings, fp16
__device__ __half g_QKh[TOK * 2 * DM];         // [t][0:1024]=Q, [t][1024:2048]=K
__device__ __half g_Vt[DM * TOK];              // V transposed: Vt[d][b*SEQ+t]
__device__ __half g_Sh[NBATCH * SEQ * SEQ];    // causal scores, fp16
__device__ __half g_Oh[TOK * DM];              // attention out / 512, fp16
__device__ __half g_Wh[NVOCAB * DM];           // fp16 wo
__device__ __half g_Wqk[2 * DM * DM];          // [wq; wk] fp16
__device__ __half g_Wv[DM * DM];
__device__ float  g_bqk[2 * DM];               // [bq; bk]

__device__ __forceinline__ uint32_t smem_u32(const void* p) {
    uint32_t a;
    asm("{ .reg .u64 t; cvta.to.shared.u64 t, %1; cvt.u32.u64 %0, t; }" : "=r"(a) : "l"(p));
    return a;
}

__device__ __forceinline__ void mma16h(float* c, const uint32_t* a, const uint32_t* b) {
    asm volatile(
        "mma.sync.aligned.m16n8k16.row.col.f32.f16.f16.f32 "
        "{%0,%1,%2,%3}, {%4,%5,%6,%7}, {%8,%9}, {%0,%1,%2,%3};\n"
        : "+f"(c[0]), "+f"(c[1]), "+f"(c[2]), "+f"(c[3])
        : "r"(a[0]), "r"(a[1]), "r"(a[2]), "r"(a[3]), "r"(b[0]), "r"(b[1]));
}

__device__ __forceinline__ void ldsm4(uint32_t* r, uint32_t addr) {
    asm volatile("ldmatrix.sync.aligned.m8n8.x4.shared.b16 {%0,%1,%2,%3}, [%4];"
        : "=r"(r[0]), "=r"(r[1]), "=r"(r[2]), "=r"(r[3]) : "r"(addr));
}

__device__ __forceinline__ void cp16(uint32_t smem, const void* g) {
    asm volatile("cp.async.cg.shared.global [%0], [%1], 16;" :: "r"(smem), "l"(g) : "memory");
}

// ---- tile constants: 128x256 CTA tile, K-chunk 64, 3 stages ----
namespace lh {
constexpr int PITCH     = 144;                // 128B data (64 fp16) + 16B pad
constexpr int A_BYTES   = 128 * PITCH;        // 18432
constexpr int B_BYTES   = 256 * PITCH;        // 36864
constexpr int STG_BYTES = A_BYTES + B_BYTES;  // 55296
constexpr int SMEM_TOT  = 3 * STG_BYTES;      // 165888
}

// ============================================================================
// Unified fp16 NT GEMM: C[gridM*128, gridN*256] = A @ B^T (+ epilogue), fp16 out
// A: [M, lda] row-major fp16 (K contiguous).  B: [N, ldb] row-major fp16.
// EPI: 0 = +colbias then elu+1, 2 = causal mask (zero col>row),
//      5 = +rowbias, 6 = scale by 1/512.
// TRIK: truncate K loop to bm+128.  Az/Bz/Cz: blockIdx.z offsets in half units.
// ============================================================================
template<int EPI, bool TRIK>
__global__ void __launch_bounds__(256, 1)
gemm_h(const __half* __restrict__ A, int lda,
       const __half* __restrict__ B, int ldb,
       const float* __restrict__ bias,
       __half* __restrict__ C, int ldc,
       int K, long long Az, long long Bz, long long Cz)
{
    A += (size_t)blockIdx.z * Az;
    B += (size_t)blockIdx.z * Bz;
    C += (size_t)blockIdx.z * Cz;

    const int bm = blockIdx.x * 128;
    const int bn = blockIdx.y * 256;
    if (EPI == 2 && bn > bm + 127) return;   // fully-masked tile: never read later

    extern __shared__ char smem[];
    const uint32_t sb = smem_u32(smem);
    const int tid  = threadIdx.x;
    const int lane = tid & 31;
    const int warp = tid >> 5;
    const int wm   = (warp >> 2) * 64;
    const int wn   = (warp & 3) * 64;

    const int g = lane >> 3;
    const uint32_t frOff = (uint32_t)(((lane & 7) + (g & 1) * 8) * lh::PITCH + (g >> 1) * 16);

    float acc[4][8][4];
    #pragma unroll
    for (int mt = 0; mt < 4; mt++)
        #pragma unroll
        for (int nt = 0; nt < 8; nt++)
            #pragma unroll
            for (int r = 0; r < 4; r++) acc[mt][nt][r] = 0.f;

    const __half* Ag = A + (size_t)bm * lda;
    const __half* Bg = B + (size_t)bn * ldb;

    int nk = K / 64;
    if (TRIK) { int kl = bm + 128; if (kl < K) nk = kl / 64; }

    auto load_stage = [&](int st) {
        const uint32_t base = sb + (st % 3) * lh::STG_BYTES;
        const int kb = st * 64;
        #pragma unroll
        for (int i = 0; i < 4; i++) {               // A: 128 rows x 8 16B chunks
            int idx = tid + i * 256;
            int row = idx >> 3, ch = idx & 7;
            cp16(base + row * lh::PITCH + ch * 16, Ag + (size_t)row * lda + kb + ch * 8);
        }
        const uint32_t bb = base + lh::A_BYTES;
        #pragma unroll
        for (int i = 0; i < 8; i++) {               // B: 256 rows x 8 16B chunks
            int idx = tid + i * 256;
            int row = idx >> 3, ch = idx & 7;
            cp16(bb + row * lh::PITCH + ch * 16, Bg + (size_t)row * ldb + kb + ch * 8);
        }
        asm volatile("cp.async.commit_group;" ::: "memory");
    };

    load_stage(0);
    if (nk > 1) load_stage(1); else asm volatile("cp.async.commit_group;" ::: "memory");

    for (int ck = 0; ck < nk; ck++) {
        // committed = 2 + ck; wait_group 1 => complete >= ck+1 (stage ck ready)
        asm volatile("cp.async.wait_group 1;" ::: "memory");
        __syncthreads();
        if (ck + 2 < nk) load_stage(ck + 2);
        else asm volatile("cp.async.commit_group;" ::: "memory");

        const uint32_t sa  = sb + (ck % 3) * lh::STG_BYTES;
        const uint32_t sbb = sa + lh::A_BYTES;
        #pragma unroll
        for (int ks = 0; ks < 4; ks++) {            // four k16 steps per chunk
            uint32_t af[4][4], bf[8][2];
            #pragma unroll
            for (int mt = 0; mt < 4; mt++)
                ldsm4(af[mt], sa + (wm + mt * 16) * lh::PITCH + ks * 32 + frOff);
            #pragma unroll
            for (int p = 0; p < 4; p++) {
                uint32_t t4[4];
                ldsm4(t4, sbb + (wn + p * 16) * lh::PITCH + ks * 32 + frOff);
                bf[2 * p][0]     = t4[0]; bf[2 * p][1]     = t4[2];
                bf[2 * p + 1][0] = t4[1]; bf[2 * p + 1][1] = t4[3];
            }
            #pragma unroll
            for (int mt = 0; mt < 4; mt++)
                #pragma unroll
                for (int nt = 0; nt < 8; nt++)
                    mma16h(acc[mt][nt], af[mt], bf[nt]);
        }
    }

    // ---- epilogue: direct fp16 fragment stores ----
    #pragma unroll
    for (int mt = 0; mt < 4; mt++) {
        #pragma unroll
        for (int nt = 0; nt < 8; nt++) {
            int r = bm + wm + mt * 16 + (lane >> 2);
            int c = bn + wn + nt * 8 + ((lane & 3) << 1);
            float v[4] = {acc[mt][nt][0], acc[mt][nt][1], acc[mt][nt][2], acc[mt][nt][3]};
            if (EPI == 0) {
                float b0 = bias[c], b1 = bias[c + 1];
                v[0] += b0; v[1] += b1; v[2] += b0; v[3] += b1;
                #pragma unroll
                for (int j = 0; j < 4; j++)
                    v[j] = (v[j] > 0.f) ? (v[j] + 1.f) : expf(v[j]);
            } else if (EPI == 5) {
                float b0 = bias[r], b1 = bias[r + 8];
                v[0] += b0; v[1] += b0; v[2] += b1; v[3] += b1;
            } else if (EPI == 2) {
                if (c     > r)     v[0] = 0.f;
                if (c + 1 > r)     v[1] = 0.f;
                if (c     > r + 8) v[2] = 0.f;
                if (c + 1 > r + 8) v[3] = 0.f;
            } else if (EPI == 6) {
                #pragma unroll
                for (int j = 0; j < 4; j++) v[j] *= O_SCALE_INV;
            }
            *(__half2*)&C[(size_t)r * ldc + c]       = __floats2half2_rn(v[0], v[1]);
            *(__half2*)&C[(size_t)(r + 8) * ldc + c] = __floats2half2_rn(v[2], v[3]);
        }
    }
}

// ============================================================================
// fp16 logits GEMM: C[4096,32000] = (A/512)h @ Bh^T * 512 + bias  (fp32 out)
// ============================================================================
__global__ void __launch_bounds__(256, 1)
logits_fp16(const __half* __restrict__ A, const __half* __restrict__ B,
            const float* __restrict__ bias, float* __restrict__ C)
{
    extern __shared__ char smem[];
    const uint32_t sb = smem_u32(smem);
    const int tid  = threadIdx.x;
    const int lane = tid & 31;
    const int warp = tid >> 5;
    const int wm   = (warp >> 2) * 64;
    const int wn   = (warp & 3) * 64;
    const int bm   = blockIdx.x * 128;
    const int bn   = blockIdx.y * 256;

    const int g = lane >> 3;
    const uint32_t frOff = (uint32_t)(((lane & 7) + (g & 1) * 8) * lh::PITCH + (g >> 1) * 16);

    float acc[4][8][4];
    #pragma unroll
    for (int mt = 0; mt < 4; mt++)
        #pragma unroll
        for (int nt = 0; nt < 8; nt++)
            #pragma unroll
            for (int r = 0; r < 4; r++) acc[mt][nt][r] = 0.f;

    const __half* Ag = A + (size_t)bm * DM;
    const __half* Bg = B + (size_t)bn * DM;

    auto load_stage = [&](int st) {
        const uint32_t base = sb + (st % 3) * lh::STG_BYTES;
        const int kb = st * 64;
        #pragma unroll
        for (int i = 0; i < 4; i++) {
            int idx = tid + i * 256;
            int row = idx >> 3, ch = idx & 7;
            cp16(base + row * lh::PITCH + ch * 16, Ag + (size_t)row * DM + kb + ch * 8);
        }
        const uint32_t bb = base + lh::A_BYTES;
        #pragma unroll
        for (int i = 0; i < 8; i++) {
            int idx = tid + i * 256;
            int row = idx >> 3, ch = idx & 7;
            cp16(bb + row * lh::PITCH + ch * 16, Bg + (size_t)row * DM + kb + ch * 8);
        }
        asm volatile("cp.async.commit_group;" ::: "memory");
    };

    const int NK = DM / 64;    // 16
    load_stage(0); load_stage(1);

    for (int ck = 0; ck < NK; ck++) {
        asm volatile("cp.async.wait_group 1;" ::: "memory");
        __syncthreads();
        if (ck + 2 < NK) load_stage(ck + 2);
        else asm volatile("cp.async.commit_group;" ::: "memory");

        const uint32_t sa  = sb + (ck % 3) * lh::STG_BYTES;
        const uint32_t sbb = sa + lh::A_BYTES;
        #pragma unroll
        for (int ks = 0; ks < 4; ks++) {
            uint32_t af[4][4], bf[8][2];
            #pragma unroll
            for (int mt = 0; mt < 4; mt++)
                ldsm4(af[mt], sa + (wm + mt * 16) * lh::PITCH + ks * 32 + frOff);
            #pragma unroll
            for (int p = 0; p < 4; p++) {
                uint32_t t4[4];
                ldsm4(t4, sbb + (wn + p * 16) * lh::PITCH + ks * 32 + frOff);
                bf[2 * p][0]     = t4[0]; bf[2 * p][1]     = t4[2];
                bf[2 * p + 1][0] = t4[1]; bf[2 * p + 1][1] = t4[3];
            }
            #pragma unroll
            for (int mt = 0; mt < 4; mt++)
                #pragma unroll
                for (int nt = 0; nt < 8; nt++)
                    mma16h(acc[mt][nt], af[mt], bf[nt]);
        }
    }

    // ---- epilogue: regs -> smem (per 128-col half) -> coalesced float4 stores ----
    float* buf = (float*)smem;                     // [128][136]
    const int whalf = (warp & 3) >> 1;
    for (int h = 0; h < 2; h++) {
        __syncthreads();
        if (whalf == h) {
            const int cb = wn - h * 128;
            #pragma unroll
            for (int mt = 0; mt < 4; mt++) {
                #pragma unroll
                for (int nt = 0; nt < 8; nt++) {
                    int rr = wm + mt * 16 + (lane >> 2);
                    int cc = cb + nt * 8 + ((lane & 3) << 1);
                    *(float2*)&buf[rr * 136 + cc]       = make_float2(acc[mt][nt][0], acc[mt][nt][1]);
                    *(float2*)&buf[(rr + 8) * 136 + cc] = make_float2(acc[mt][nt][2], acc[mt][nt][3]);
                }
            }
        }
        __syncthreads();
        #pragma unroll
        for (int it = 0; it < 16; it++) {
            int i  = tid + it * 256;
            int rr = i >> 5;
            int c  = (i & 31) * 4;
            const float* sr = buf + rr * 136 + c;
            const float4 bv = *(const float4*)(bias + bn + h * 128 + c);
            float4 v;
            v.x = sr[0] * O_SCALE + bv.x;
            v.y = sr[1] * O_SCALE + bv.y;
            v.z = sr[2] * O_SCALE + bv.z;
            v.w = sr[3] * O_SCALE + bv.w;
            *(float4*)&C[(size_t)(bm + rr) * NVOCAB + bn + h * 128 + c] = v;
        }
    }
}

// ============================================================================
// conversion / gather kernels
// ============================================================================
__global__ void __launch_bounds__(256)
cvt_f2h(const float* __restrict__ in, __half* __restrict__ out)
{
    size_t i = ((size_t)blockIdx.x * 256 + threadIdx.x) * 8;
    float4 v0 = *(const float4*)(in + i);
    float4 v1 = *(const float4*)(in + i + 4);
    __half2 h[4];
    h[0] = __floats2half2_rn(v0.x, v0.y);
    h[1] = __floats2half2_rn(v0.z, v0.w);
    h[2] = __floats2half2_rn(v1.x, v1.y);
    h[3] = __floats2half2_rn(v1.z, v1.w);
    *(uint4*)(out + i) = *(uint4*)h;
}

__global__ void __launch_bounds__(256)
concat_bias(const float* __restrict__ bq, const float* __restrict__ bk,
            float* __restrict__ out)
{
    int i = blockIdx.x * 256 + threadIdx.x;
    out[i] = (i < DM) ? bq[i] : bk[i - DM];
}

__global__ void __launch_bounds__(256)
gather_cvt(const int* __restrict__ x, const float* __restrict__ emb,
           __half* __restrict__ out)
{
    const int t = blockIdx.x;
    const int d = threadIdx.x * 4;
    const float4 v = *(const float4*)(emb + (size_t)x[t] * DM + d);
    __half2 h0 = __floats2half2_rn(v.x, v.y);
    __half2 h1 = __floats2half2_rn(v.z, v.w);
    uint2 u;
    u.x = *(uint32_t*)&h0;
    u.y = *(uint32_t*)&h1;
    *(uint2*)(out + (size_t)t * DM + d) = u;
}

extern "C" void kernel_launch(void* const* d_in, const int* in_sizes, int n_in,
                              void* d_out, int out_size)
{
    (void)in_sizes; (void)n_in; (void)out_size;
    const int*   x   = (const int*)  d_in[0];
    const float* emb = (const float*)d_in[1];
    const float* wq  = (const float*)d_in[2];
    const float* bq  = (const float*)d_in[3];
    const float* wk  = (const float*)d_in[4];
    const float* bk  = (const float*)d_in[5];
    const float* wv  = (const float*)d_in[6];
    const float* bv  = (const float*)d_in[7];
    const float* wo  = (const float*)d_in[8];
    const float* bo  = (const float*)d_in[9];
    float* out = (float*)d_out;

    __half *eh, *QKh, *Vt, *Sh, *Oh, *Wh, *Wqk, *Wv;
    float* bqk;
    cudaGetSymbolAddress((void**)&eh,  g_eh);
    cudaGetSymbolAddress((void**)&QKh, g_QKh);
    cudaGetSymbolAddress((void**)&Vt,  g_Vt);
    cudaGetSymbolAddress((void**)&Sh,  g_Sh);
    cudaGetSymbolAddress((void**)&Oh,  g_Oh);
    cudaGetSymbolAddress((void**)&Wh,  g_Wh);
    cudaGetSymbolAddress((void**)&Wqk, g_Wqk);
    cudaGetSymbolAddress((void**)&Wv,  g_Wv);
    cudaGetSymbolAddress((void**)&bqk, g_bqk);

    cudaFuncSetAttribute(logits_fp16,
                         cudaFuncAttributeMaxDynamicSharedMemorySize, lh::SMEM_TOT);
    cudaFuncSetAttribute(gemm_h<0, false>,
                         cudaFuncAttributeMaxDynamicSharedMemorySize, lh::SMEM_TOT);
    cudaFuncSetAttribute(gemm_h<5, false>,
                         cudaFuncAttributeMaxDynamicSharedMemorySize, lh::SMEM_TOT);
    cudaFuncSetAttribute(gemm_h<2, false>,
                         cudaFuncAttributeMaxDynamicSharedMemorySize, lh::SMEM_TOT);
    cudaFuncSetAttribute(gemm_h<6, true>,
                         cudaFuncAttributeMaxDynamicSharedMemorySize, lh::SMEM_TOT);

    dim3 thr(256);

    // 0) conversions
    cvt_f2h<<<NVOCAB * DM / (256 * 8), thr>>>(wo, Wh);
    cvt_f2h<<<DM * DM / (256 * 8), thr>>>(wq, Wqk);
    cvt_f2h<<<DM * DM / (256 * 8), thr>>>(wk, Wqk + (size_t)DM * DM);
    cvt_f2h<<<DM * DM / (256 * 8), thr>>>(wv, Wv);
    concat_bias<<<2 * DM / 256, thr>>>(bq, bk, bqk);
    gather_cvt<<<TOK, thr>>>(x, emb, eh);

    // 1) fused Q+K projection: QKh[4096,2048] = e_h @ Wqk^T, elu+1 + bias
    dim3 gQK(TOK / 128, 2 * DM / 256, 1);
    gemm_h<0, false><<<gQK, thr, lh::SMEM_TOT>>>(eh, DM, Wqk, DM, bqk, QKh, 2 * DM, DM, 0, 0, 0);

    // 2) V pre-transposed: Vt[1024,4096] = wv @ e_h^T + bv (row bias)
    dim3 gVt(DM / 128, TOK / 256, 1);
    gemm_h<5, false><<<gVt, thr, lh::SMEM_TOT>>>(Wv, DM, eh, DM, bv, Vt, TOK, DM, 0, 0, 0);

    // 3) causal scores per batch: S_b = tril(Q_b @ K_b^T), fp16
    dim3 gSc(SEQ / 128, SEQ / 256, NBATCH);
    gemm_h<2, false><<<gSc, thr, lh::SMEM_TOT>>>(
        QKh, 2 * DM, QKh + DM, 2 * DM, nullptr, Sh, SEQ, DM,
        (long long)SEQ * 2 * DM, (long long)SEQ * 2 * DM, (long long)SEQ * SEQ);

    // 4) O_b = (S_b @ Vt_b^T) / 512, TRIK-truncated K loop
    dim3 gAV(SEQ / 128, DM / 256, NBATCH);
    gemm_h<6, true><<<gAV, thr, lh::SMEM_TOT>>>(
        Sh, SEQ, Vt, TOK, nullptr, Oh, DM, SEQ,
        (long long)SEQ * SEQ, (long long)SEQ, (long long)SEQ * DM);

    // 5) logits: [4096,32000] = (Oh @ Wh^T) * 512 + bo
    dim3 gLg(TOK / 128, NVOCAB / 256, 1);
    logits_fp16<<<gLg, thr, lh::SMEM_TOT>>>(Oh, Wh, bo, out);
}

// round 9
// speedup vs baseline: 2.7202x; 1.0106x over previous
#include <cuda_runtime.h>
#include <cuda_fp16.h>
#include <cstdint>

namespace {
constexpr int DM     = 1024;
constexpr int SEQ    = 2048;
constexpr int NBATCH = 2;
constexpr int TOK    = SEQ * NBATCH;   // 4096
constexpr int NVOCAB = 32000;
constexpr float O_SCALE     = 512.f;   // O stored as O/512 in fp16 (exact pow2)
constexpr float O_SCALE_INV = 1.f / 512.f;
}

// ---- scratch (device globals: allocation-free) ----
__device__ __half g_eh[TOK * DM];              // gathered embeddings, fp16
__device__ __half g_QKh[TOK * 2 * DM];         // [t][0:1024]=Q, [t][1024:2048]=K
__device__ __half g_Vt[DM * TOK];              // V transposed: Vt[d][b*SEQ+t]
__device__ __half g_Sh[NBATCH * SEQ * SEQ];    // causal scores, fp16
__device__ __half g_Oh[TOK * DM];              // attention out / 512, fp16
__device__ __half g_Wh[NVOCAB * DM];           // fp16 wo
__device__ __half g_Wqk[2 * DM * DM];          // [wq; wk] fp16
__device__ __half g_Wv[DM * DM];
__device__ float  g_bqk[2 * DM];               // [bq; bk]

__device__ __forceinline__ uint32_t smem_u32(const void* p) {
    uint32_t a;
    asm("{ .reg .u64 t; cvta.to.shared.u64 t, %1; cvt.u32.u64 %0, t; }" : "=r"(a) : "l"(p));
    return a;
}

__device__ __forceinline__ void mma16h(float* c, const uint32_t* a, const uint32_t* b) {
    asm volatile(
        "mma.sync.aligned.m16n8k16.row.col.f32.f16.f16.f32 "
        "{%0,%1,%2,%3}, {%4,%5,%6,%7}, {%8,%9}, {%0,%1,%2,%3};\n"
        : "+f"(c[0]), "+f"(c[1]), "+f"(c[2]), "+f"(c[3])
        : "r"(a[0]), "r"(a[1]), "r"(a[2]), "r"(a[3]), "r"(b[0]), "r"(b[1]));
}

__device__ __forceinline__ void ldsm4(uint32_t* r, uint32_t addr) {
    asm volatile("ldmatrix.sync.aligned.m8n8.x4.shared.b16 {%0,%1,%2,%3}, [%4];"
        : "=r"(r[0]), "=r"(r[1]), "=r"(r[2]), "=r"(r[3]) : "r"(addr));
}

__device__ __forceinline__ void cp16(uint32_t smem, const void* g) {
    asm volatile("cp.async.cg.shared.global [%0], [%1], 16;" :: "r"(smem), "l"(g) : "memory");
}

// ---- tile constants: 128x256 CTA tile, K-chunk 64, 3 stages ----
namespace lh {
constexpr int PITCH     = 144;                // 128B data (64 fp16) + 16B pad
constexpr int A_BYTES   = 128 * PITCH;        // 18432
constexpr int B_BYTES   = 256 * PITCH;        // 36864
constexpr int STG_BYTES = A_BYTES + B_BYTES;  // 55296
constexpr int SMEM_TOT  = 3 * STG_BYTES;      // 165888
}

// ============================================================================
// Unified fp16 NT GEMM (non-persistent, small GEMMs):
// C[gridM*128, gridN*256] = A @ B^T (+ epilogue), fp16 out
// EPI: 0 = +colbias then elu+1, 2 = causal mask, 5 = +rowbias, 6 = x(1/512).
// TRIK: truncate K loop to bm+128.  Az/Bz/Cz: blockIdx.z offsets, half units.
// ============================================================================
template<int EPI, bool TRIK>
__global__ void __launch_bounds__(256, 1)
gemm_h(const __half* __restrict__ A, int lda,
       const __half* __restrict__ B, int ldb,
       const float* __restrict__ bias,
       __half* __restrict__ C, int ldc,
       int K, long long Az, long long Bz, long long Cz)
{
    A += (size_t)blockIdx.z * Az;
    B += (size_t)blockIdx.z * Bz;
    C += (size_t)blockIdx.z * Cz;

    const int bm = blockIdx.x * 128;
    const int bn = blockIdx.y * 256;
    if (EPI == 2 && bn > bm + 127) return;   // fully-masked tile: never read later

    extern __shared__ char smem[];
    const uint32_t sb = smem_u32(smem);
    const int tid  = threadIdx.x;
    const int lane = tid & 31;
    const int warp = tid >> 5;
    const int wm   = (warp >> 2) * 64;
    const int wn   = (warp & 3) * 64;

    const int g = lane >> 3;
    const uint32_t frOff = (uint32_t)(((lane & 7) + (g & 1) * 8) * lh::PITCH + (g >> 1) * 16);

    float acc[4][8][4];
    #pragma unroll
    for (int mt = 0; mt < 4; mt++)
        #pragma unroll
        for (int nt = 0; nt < 8; nt++)
            #pragma unroll
            for (int r = 0; r < 4; r++) acc[mt][nt][r] = 0.f;

    const __half* Ag = A + (size_t)bm * lda;
    const __half* Bg = B + (size_t)bn * ldb;

    int nk = K / 64;
    if (TRIK) { int kl = bm + 128; if (kl < K) nk = kl / 64; }

    auto load_stage = [&](int st) {
        const uint32_t base = sb + (st % 3) * lh::STG_BYTES;
        const int kb = st * 64;
        #pragma unroll
        for (int i = 0; i < 4; i++) {               // A: 128 rows x 8 16B chunks
            int idx = tid + i * 256;
            int row = idx >> 3, ch = idx & 7;
            cp16(base + row * lh::PITCH + ch * 16, Ag + (size_t)row * lda + kb + ch * 8);
        }
        const uint32_t bb = base + lh::A_BYTES;
        #pragma unroll
        for (int i = 0; i < 8; i++) {               // B: 256 rows x 8 16B chunks
            int idx = tid + i * 256;
            int row = idx >> 3, ch = idx & 7;
            cp16(bb + row * lh::PITCH + ch * 16, Bg + (size_t)row * ldb + kb + ch * 8);
        }
        asm volatile("cp.async.commit_group;" ::: "memory");
    };

    load_stage(0);
    if (nk > 1) load_stage(1); else asm volatile("cp.async.commit_group;" ::: "memory");

    for (int ck = 0; ck < nk; ck++) {
        asm volatile("cp.async.wait_group 1;" ::: "memory");
        __syncthreads();
        if (ck + 2 < nk) load_stage(ck + 2);
        else asm volatile("cp.async.commit_group;" ::: "memory");

        const uint32_t sa  = sb + (ck % 3) * lh::STG_BYTES;
        const uint32_t sbb = sa + lh::A_BYTES;
        #pragma unroll
        for (int ks = 0; ks < 4; ks++) {
            uint32_t af[4][4], bf[8][2];
            #pragma unroll
            for (int mt = 0; mt < 4; mt++)
                ldsm4(af[mt], sa + (wm + mt * 16) * lh::PITCH + ks * 32 + frOff);
            #pragma unroll
            for (int p = 0; p < 4; p++) {
                uint32_t t4[4];
                ldsm4(t4, sbb + (wn + p * 16) * lh::PITCH + ks * 32 + frOff);
                bf[2 * p][0]     = t4[0]; bf[2 * p][1]     = t4[2];
                bf[2 * p + 1][0] = t4[1]; bf[2 * p + 1][1] = t4[3];
            }
            #pragma unroll
            for (int mt = 0; mt < 4; mt++)
                #pragma unroll
                for (int nt = 0; nt < 8; nt++)
                    mma16h(acc[mt][nt], af[mt], bf[nt]);
        }
    }

    #pragma unroll
    for (int mt = 0; mt < 4; mt++) {
        #pragma unroll
        for (int nt = 0; nt < 8; nt++) {
            int r = bm + wm + mt * 16 + (lane >> 2);
            int c = bn + wn + nt * 8 + ((lane & 3) << 1);
            float v[4] = {acc[mt][nt][0], acc[mt][nt][1], acc[mt][nt][2], acc[mt][nt][3]};
            if (EPI == 0) {
                float b0 = bias[c], b1 = bias[c + 1];
                v[0] += b0; v[1] += b1; v[2] += b0; v[3] += b1;
                #pragma unroll
                for (int j = 0; j < 4; j++)
                    v[j] = (v[j] > 0.f) ? (v[j] + 1.f) : expf(v[j]);
            } else if (EPI == 5) {
                float b0 = bias[r], b1 = bias[r + 8];
                v[0] += b0; v[1] += b0; v[2] += b1; v[3] += b1;
            } else if (EPI == 2) {
                if (c     > r)     v[0] = 0.f;
                if (c + 1 > r)     v[1] = 0.f;
                if (c     > r + 8) v[2] = 0.f;
                if (c + 1 > r + 8) v[3] = 0.f;
            } else if (EPI == 6) {
                #pragma unroll
                for (int j = 0; j < 4; j++) v[j] *= O_SCALE_INV;
            }
            *(__half2*)&C[(size_t)r * ldc + c]       = __floats2half2_rn(v[0], v[1]);
            *(__half2*)&C[(size_t)(r + 8) * ldc + c] = __floats2half2_rn(v[2], v[3]);
        }
    }
}

// ============================================================================
// PERSISTENT fp16 logits GEMM: C[4096,32000] = (A/512)h @ Bh^T * 512 + bias
// grid = #SMs; each CTA streams chunks across its tiles (no pipeline drain).
// Tile map: tile t -> bm = (t % 32)*128, bn = (t / 32)*256.  16 chunks/tile.
// ============================================================================
__global__ void __launch_bounds__(256, 1)
logits_persist(const __half* __restrict__ A, const __half* __restrict__ B,
               const float* __restrict__ bias, float* __restrict__ C,
               int ntiles, int gridsz)
{
    extern __shared__ char smem[];
    const uint32_t sb = smem_u32(smem);
    const int tid  = threadIdx.x;
    const int lane = tid & 31;
    const int warp = tid >> 5;
    const int wm   = (warp >> 2) * 64;
    const int wn   = (warp & 3) * 64;

    const int g = lane >> 3;
    const uint32_t frOff = (uint32_t)(((lane & 7) + (g & 1) * 8) * lh::PITCH + (g >> 1) * 16);

    if ((int)blockIdx.x >= ntiles) return;
    const int nt_mine = (ntiles - (int)blockIdx.x + gridsz - 1) / gridsz;
    const int NC = nt_mine * 16;

    float acc[4][8][4];
    #pragma unroll
    for (int mt = 0; mt < 4; mt++)
        #pragma unroll
        for (int nt = 0; nt < 8; nt++)
            #pragma unroll
            for (int r = 0; r < 4; r++) acc[mt][nt][r] = 0.f;

    auto load_chunk = [&](int cg) {
        const int tile = (int)blockIdx.x + (cg >> 4) * gridsz;
        const int bm = (tile & 31) << 7;
        const int bn = (tile >> 5) << 8;
        const int kb = (cg & 15) << 6;
        const __half* Ag = A + (size_t)bm * DM + kb;
        const __half* Bg = B + (size_t)bn * DM + kb;
        const uint32_t base = sb + (cg % 3) * lh::STG_BYTES;
        #pragma unroll
        for (int i = 0; i < 4; i++) {
            int idx = tid + i * 256;
            int row = idx >> 3, ch = idx & 7;
            cp16(base + row * lh::PITCH + ch * 16, Ag + (size_t)row * DM + ch * 8);
        }
        const uint32_t bb = base + lh::A_BYTES;
        #pragma unroll
        for (int i = 0; i < 8; i++) {
            int idx = tid + i * 256;
            int row = idx >> 3, ch = idx & 7;
            cp16(bb + row * lh::PITCH + ch * 16, Bg + (size_t)row * DM + ch * 8);
        }
        asm volatile("cp.async.commit_group;" ::: "memory");
    };

    load_chunk(0); load_chunk(1);   // NC >= 16, always valid

    for (int cg = 0; cg < NC; cg++) {
        // committed = cg + 2; wait_group 1 => completed >= cg+1 => stage cg ready
        asm volatile("cp.async.wait_group 1;" ::: "memory");
        __syncthreads();
        if (cg + 2 < NC) load_chunk(cg + 2);
        else asm volatile("cp.async.commit_group;" ::: "memory");

        const uint32_t sa  = sb + (cg % 3) * lh::STG_BYTES;
        const uint32_t sbb = sa + lh::A_BYTES;
        #pragma unroll
        for (int ks = 0; ks < 4; ks++) {
            uint32_t af[4][4], bf[8][2];
            #pragma unroll
            for (int mt = 0; mt < 4; mt++)
                ldsm4(af[mt], sa + (wm + mt * 16) * lh::PITCH + ks * 32 + frOff);
            #pragma unroll
            for (int p = 0; p < 4; p++) {
                uint32_t t4[4];
                ldsm4(t4, sbb + (wn + p * 16) * lh::PITCH + ks * 32 + frOff);
                bf[2 * p][0]     = t4[0]; bf[2 * p][1]     = t4[2];
                bf[2 * p + 1][0] = t4[1]; bf[2 * p + 1][1] = t4[3];
            }
            #pragma unroll
            for (int mt = 0; mt < 4; mt++)
                #pragma unroll
                for (int nt = 0; nt < 8; nt++)
                    mma16h(acc[mt][nt], af[mt], bf[nt]);
        }

        if ((cg & 15) == 15) {
            // tile finished: direct coalesced fragment stores (overlap next loads)
            const int tile = (int)blockIdx.x + (cg >> 4) * gridsz;
            const int bm = (tile & 31) << 7;
            const int bn = (tile >> 5) << 8;
            #pragma unroll
            for (int mt = 0; mt < 4; mt++) {
                #pragma unroll
                for (int nt = 0; nt < 8; nt++) {
                    int r = bm + wm + mt * 16 + (lane >> 2);
                    int c = bn + wn + nt * 8 + ((lane & 3) << 1);
                    const float2 bv = *(const float2*)(bias + c);
                    *(float2*)&C[(size_t)r * NVOCAB + c] = make_float2(
                        acc[mt][nt][0] * O_SCALE + bv.x,
                        acc[mt][nt][1] * O_SCALE + bv.y);
                    *(float2*)&C[(size_t)(r + 8) * NVOCAB + c] = make_float2(
                        acc[mt][nt][2] * O_SCALE + bv.x,
                        acc[mt][nt][3] * O_SCALE + bv.y);
                    acc[mt][nt][0] = 0.f; acc[mt][nt][1] = 0.f;
                    acc[mt][nt][2] = 0.f; acc[mt][nt][3] = 0.f;
                }
            }
        }
    }
}

// ============================================================================
// conversion / gather kernels
// ============================================================================
__global__ void __launch_bounds__(256)
cvt_f2h(const float* __restrict__ in, __half* __restrict__ out)
{
    size_t i = ((size_t)blockIdx.x * 256 + threadIdx.x) * 16;
    #pragma unroll
    for (int p = 0; p < 2; p++) {
        float4 v0 = *(const float4*)(in + i + p * 8);
        float4 v1 = *(const float4*)(in + i + p * 8 + 4);
        __half2 h[4];
        h[0] = __floats2half2_rn(v0.x, v0.y);
        h[1] = __floats2half2_rn(v0.z, v0.w);
        h[2] = __floats2half2_rn(v1.x, v1.y);
        h[3] = __floats2half2_rn(v1.z, v1.w);
        *(uint4*)(out + i + p * 8) = *(uint4*)h;
    }
}

__global__ void __launch_bounds__(256)
concat_bias(const float* __restrict__ bq, const float* __restrict__ bk,
            float* __restrict__ out)
{
    int i = blockIdx.x * 256 + threadIdx.x;
    out[i] = (i < DM) ? bq[i] : bk[i - DM];
}

__global__ void __launch_bounds__(256)
gather_cvt(const int* __restrict__ x, const float* __restrict__ emb,
           __half* __restrict__ out)
{
    const int t = blockIdx.x;
    const int d = threadIdx.x * 4;
    const float4 v = *(const float4*)(emb + (size_t)x[t] * DM + d);
    __half2 h0 = __floats2half2_rn(v.x, v.y);
    __half2 h1 = __floats2half2_rn(v.z, v.w);
    uint2 u;
    u.x = *(uint32_t*)&h0;
    u.y = *(uint32_t*)&h1;
    *(uint2*)(out + (size_t)t * DM + d) = u;
}

extern "C" void kernel_launch(void* const* d_in, const int* in_sizes, int n_in,
                              void* d_out, int out_size)
{
    (void)in_sizes; (void)n_in; (void)out_size;
    const int*   x   = (const int*)  d_in[0];
    const float* emb = (const float*)d_in[1];
    const float* wq  = (const float*)d_in[2];
    const float* bq  = (const float*)d_in[3];
    const float* wk  = (const float*)d_in[4];
    const float* bk  = (const float*)d_in[5];
    const float* wv  = (const float*)d_in[6];
    const float* bv  = (const float*)d_in[7];
    const float* wo  = (const float*)d_in[8];
    const float* bo  = (const float*)d_in[9];
    float* out = (float*)d_out;

    __half *eh, *QKh, *Vt, *Sh, *Oh, *Wh, *Wqk, *Wv;
    float* bqk;
    cudaGetSymbolAddress((void**)&eh,  g_eh);
    cudaGetSymbolAddress((void**)&QKh, g_QKh);
    cudaGetSymbolAddress((void**)&Vt,  g_Vt);
    cudaGetSymbolAddress((void**)&Sh,  g_Sh);
    cudaGetSymbolAddress((void**)&Oh,  g_Oh);
    cudaGetSymbolAddress((void**)&Wh,  g_Wh);
    cudaGetSymbolAddress((void**)&Wqk, g_Wqk);
    cudaGetSymbolAddress((void**)&Wv,  g_Wv);
    cudaGetSymbolAddress((void**)&bqk, g_bqk);

    int nsm = 148;
    cudaDeviceGetAttribute(&nsm, cudaDevAttrMultiProcessorCount, 0);

    cudaFuncSetAttribute(logits_persist,
                         cudaFuncAttributeMaxDynamicSharedMemorySize, lh::SMEM_TOT);
    cudaFuncSetAttribute(gemm_h<0, false>,
                         cudaFuncAttributeMaxDynamicSharedMemorySize, lh::SMEM_TOT);
    cudaFuncSetAttribute(gemm_h<5, false>,
                         cudaFuncAttributeMaxDynamicSharedMemorySize, lh::SMEM_TOT);
    cudaFuncSetAttribute(gemm_h<2, false>,
                         cudaFuncAttributeMaxDynamicSharedMemorySize, lh::SMEM_TOT);
    cudaFuncSetAttribute(gemm_h<6, true>,
                         cudaFuncAttributeMaxDynamicSharedMemorySize, lh::SMEM_TOT);

    dim3 thr(256);

    // 0) conversions
    cvt_f2h<<<NVOCAB * DM / (256 * 16), thr>>>(wo, Wh);
    cvt_f2h<<<DM * DM / (256 * 16), thr>>>(wq, Wqk);
    cvt_f2h<<<DM * DM / (256 * 16), thr>>>(wk, Wqk + (size_t)DM * DM);
    cvt_f2h<<<DM * DM / (256 * 16), thr>>>(wv, Wv);
    concat_bias<<<2 * DM / 256, thr>>>(bq, bk, bqk);
    gather_cvt<<<TOK, thr>>>(x, emb, eh);

    // 1) fused Q+K projection: QKh[4096,2048] = e_h @ Wqk^T, elu+1 + bias
    dim3 gQK(TOK / 128, 2 * DM / 256, 1);
    gemm_h<0, false><<<gQK, thr, lh::SMEM_TOT>>>(eh, DM, Wqk, DM, bqk, QKh, 2 * DM, DM, 0, 0, 0);

    // 2) V pre-transposed: Vt[1024,4096] = wv @ e_h^T + bv (row bias)
    dim3 gVt(DM / 128, TOK / 256, 1);
    gemm_h<5, false><<<gVt, thr, lh::SMEM_TOT>>>(Wv, DM, eh, DM, bv, Vt, TOK, DM, 0, 0, 0);

    // 3) causal scores per batch: S_b = tril(Q_b @ K_b^T), fp16
    dim3 gSc(SEQ / 128, SEQ / 256, NBATCH);
    gemm_h<2, false><<<gSc, thr, lh::SMEM_TOT>>>(
        QKh, 2 * DM, QKh + DM, 2 * DM, nullptr, Sh, SEQ, DM,
        (long long)SEQ * 2 * DM, (long long)SEQ * 2 * DM, (long long)SEQ * SEQ);

    // 4) O_b = (S_b @ Vt_b^T) / 512, TRIK-truncated K loop
    dim3 gAV(SEQ / 128, DM / 256, NBATCH);
    gemm_h<6, true><<<gAV, thr, lh::SMEM_TOT>>>(
        Sh, SEQ, Vt, TOK, nullptr, Oh, DM, SEQ,
        (long long)SEQ * SEQ, (long long)SEQ, (long long)SEQ * DM);

    // 5) logits (persistent): [4096,32000] = (Oh @ Wh^T) * 512 + bo
    const int ntiles = (TOK / 128) * (NVOCAB / 256);   // 4000
    logits_persist<<<nsm, thr, lh::SMEM_TOT>>>(Oh, Wh, bo, out, ntiles, nsm);
}

// round 10
// speedup vs baseline: 2.7674x; 1.0173x over previous
#include <cuda_runtime.h>
#include <cuda_fp16.h>
#include <cstdint>

namespace {
constexpr int DM     = 1024;
constexpr int SEQ    = 2048;
constexpr int NBATCH = 2;
constexpr int TOK    = SEQ * NBATCH;   // 4096
constexpr int NVOCAB = 32000;
constexpr float O_SCALE     = 512.f;   // O stored as O/512 in fp16 (exact pow2)
constexpr float O_SCALE_INV = 1.f / 512.f;
constexpr int NTHR = 512;              // 16 warps: 4 per SMSP for latency hiding
}

// ---- scratch (device globals: allocation-free) ----
__device__ __half g_eh[TOK * DM];              // gathered embeddings, fp16
__device__ __half g_QKh[TOK * 2 * DM];         // [t][0:1024]=Q, [t][1024:2048]=K
__device__ __half g_Vt[DM * TOK];              // V transposed: Vt[d][b*SEQ+t]
__device__ __half g_Sh[NBATCH * SEQ * SEQ];    // causal scores, fp16
__device__ __half g_Oh[TOK * DM];              // attention out / 512, fp16
__device__ __half g_Wh[NVOCAB * DM];           // fp16 wo
__device__ __half g_Wqk[2 * DM * DM];          // [wq; wk] fp16
__device__ __half g_Wv[DM * DM];
__device__ float  g_bqk[2 * DM];               // [bq; bk]

__device__ __forceinline__ uint32_t smem_u32(const void* p) {
    uint32_t a;
    asm("{ .reg .u64 t; cvta.to.shared.u64 t, %1; cvt.u32.u64 %0, t; }" : "=r"(a) : "l"(p));
    return a;
}

__device__ __forceinline__ void mma16h(float* c, const uint32_t* a, const uint32_t* b) {
    asm volatile(
        "mma.sync.aligned.m16n8k16.row.col.f32.f16.f16.f32 "
        "{%0,%1,%2,%3}, {%4,%5,%6,%7}, {%8,%9}, {%0,%1,%2,%3};\n"
        : "+f"(c[0]), "+f"(c[1]), "+f"(c[2]), "+f"(c[3])
        : "r"(a[0]), "r"(a[1]), "r"(a[2]), "r"(a[3]), "r"(b[0]), "r"(b[1]));
}

__device__ __forceinline__ void ldsm4(uint32_t* r, uint32_t addr) {
    asm volatile("ldmatrix.sync.aligned.m8n8.x4.shared.b16 {%0,%1,%2,%3}, [%4];"
        : "=r"(r[0]), "=r"(r[1]), "=r"(r[2]), "=r"(r[3]) : "r"(addr));
}

__device__ __forceinline__ void cp16(uint32_t smem, const void* g) {
    asm volatile("cp.async.cg.shared.global [%0], [%1], 16;" :: "r"(smem), "l"(g) : "memory");
}

// ---- tile constants: 128x256 CTA tile, K-chunk 64, 3 stages ----
namespace lh {
constexpr int PITCH     = 144;                // 128B data (64 fp16) + 16B pad
constexpr int A_BYTES   = 128 * PITCH;        // 18432
constexpr int B_BYTES   = 256 * PITCH;        // 36864
constexpr int STG_BYTES = A_BYTES + B_BYTES;  // 55296
constexpr int SMEM_TOT  = 3 * STG_BYTES;      // 165888
}

// ============================================================================
// Unified fp16 NT GEMM (non-persistent, small GEMMs), 512 threads:
// 16 warps, warp tile 64x32 (2 m-rows x 8 n-cols of warps).
// EPI: 0 = +colbias then elu+1, 2 = causal mask, 5 = +rowbias, 6 = x(1/512).
// TRIK: truncate K loop to bm+128.  Az/Bz/Cz: blockIdx.z offsets, half units.
// ============================================================================
template<int EPI, bool TRIK>
__global__ void __launch_bounds__(NTHR, 1)
gemm_h(const __half* __restrict__ A, int lda,
       const __half* __restrict__ B, int ldb,
       const float* __restrict__ bias,
       __half* __restrict__ C, int ldc,
       int K, long long Az, long long Bz, long long Cz)
{
    A += (size_t)blockIdx.z * Az;
    B += (size_t)blockIdx.z * Bz;
    C += (size_t)blockIdx.z * Cz;

    const int bm = blockIdx.x * 128;
    const int bn = blockIdx.y * 256;
    if (EPI == 2 && bn > bm + 127) return;   // fully-masked tile: never read later

    extern __shared__ char smem[];
    const uint32_t sb = smem_u32(smem);
    const int tid  = threadIdx.x;
    const int lane = tid & 31;
    const int warp = tid >> 5;
    const int wm   = (warp >> 3) * 64;   // 2 warp rows
    const int wn   = (warp & 7) * 32;    // 8 warp cols

    const int g = lane >> 3;
    const uint32_t frOff = (uint32_t)(((lane & 7) + (g & 1) * 8) * lh::PITCH + (g >> 1) * 16);

    float acc[4][4][4];
    #pragma unroll
    for (int mt = 0; mt < 4; mt++)
        #pragma unroll
        for (int nt = 0; nt < 4; nt++)
            #pragma unroll
            for (int r = 0; r < 4; r++) acc[mt][nt][r] = 0.f;

    const __half* Ag = A + (size_t)bm * lda;
    const __half* Bg = B + (size_t)bn * ldb;

    int nk = K / 64;
    if (TRIK) { int kl = bm + 128; if (kl < K) nk = kl / 64; }

    auto load_stage = [&](int st) {
        const uint32_t base = sb + (st % 3) * lh::STG_BYTES;
        const int kb = st * 64;
        #pragma unroll
        for (int i = 0; i < 2; i++) {               // A: 128 rows x 8 16B chunks
            int idx = tid + i * NTHR;
            int row = idx >> 3, ch = idx & 7;
            cp16(base + row * lh::PITCH + ch * 16, Ag + (size_t)row * lda + kb + ch * 8);
        }
        const uint32_t bb = base + lh::A_BYTES;
        #pragma unroll
        for (int i = 0; i < 4; i++) {               // B: 256 rows x 8 16B chunks
            int idx = tid + i * NTHR;
            int row = idx >> 3, ch = idx & 7;
            cp16(bb + row * lh::PITCH + ch * 16, Bg + (size_t)row * ldb + kb + ch * 8);
        }
        asm volatile("cp.async.commit_group;" ::: "memory");
    };

    load_stage(0);
    if (nk > 1) load_stage(1); else asm volatile("cp.async.commit_group;" ::: "memory");

    for (int ck = 0; ck < nk; ck++) {
        // committed = 2 + ck; wait_group 1 => complete >= ck+1 (stage ck ready)
        asm volatile("cp.async.wait_group 1;" ::: "memory");
        __syncthreads();
        if (ck + 2 < nk) load_stage(ck + 2);
        else asm volatile("cp.async.commit_group;" ::: "memory");

        const uint32_t sa  = sb + (ck % 3) * lh::STG_BYTES;
        const uint32_t sbb = sa + lh::A_BYTES;
        #pragma unroll
        for (int ks = 0; ks < 4; ks++) {            // four k16 steps per chunk
            uint32_t af[4][4], bf[4][2];
            #pragma unroll
            for (int mt = 0; mt < 4; mt++)
                ldsm4(af[mt], sa + (wm + mt * 16) * lh::PITCH + ks * 32 + frOff);
            #pragma unroll
            for (int p = 0; p < 2; p++) {
                uint32_t t4[4];
                ldsm4(t4, sbb + (wn + p * 16) * lh::PITCH + ks * 32 + frOff);
                bf[2 * p][0]     = t4[0]; bf[2 * p][1]     = t4[2];
                bf[2 * p + 1][0] = t4[1]; bf[2 * p + 1][1] = t4[3];
            }
            #pragma unroll
            for (int mt = 0; mt < 4; mt++)
                #pragma unroll
                for (int nt = 0; nt < 4; nt++)
                    mma16h(acc[mt][nt], af[mt], bf[nt]);
        }
    }

    #pragma unroll
    for (int mt = 0; mt < 4; mt++) {
        #pragma unroll
        for (int nt = 0; nt < 4; nt++) {
            int r = bm + wm + mt * 16 + (lane >> 2);
            int c = bn + wn + nt * 8 + ((lane & 3) << 1);
            float v[4] = {acc[mt][nt][0], acc[mt][nt][1], acc[mt][nt][2], acc[mt][nt][3]};
            if (EPI == 0) {
                float b0 = bias[c], b1 = bias[c + 1];
                v[0] += b0; v[1] += b1; v[2] += b0; v[3] += b1;
                #pragma unroll
                for (int j = 0; j < 4; j++)
                    v[j] = (v[j] > 0.f) ? (v[j] + 1.f) : expf(v[j]);
            } else if (EPI == 5) {
                float b0 = bias[r], b1 = bias[r + 8];
                v[0] += b0; v[1] += b0; v[2] += b1; v[3] += b1;
            } else if (EPI == 2) {
                if (c     > r)     v[0] = 0.f;
                if (c + 1 > r)     v[1] = 0.f;
                if (c     > r + 8) v[2] = 0.f;
                if (c + 1 > r + 8) v[3] = 0.f;
            } else if (EPI == 6) {
                #pragma unroll
                for (int j = 0; j < 4; j++) v[j] *= O_SCALE_INV;
            }
            *(__half2*)&C[(size_t)r * ldc + c]       = __floats2half2_rn(v[0], v[1]);
            *(__half2*)&C[(size_t)(r + 8) * ldc + c] = __floats2half2_rn(v[2], v[3]);
        }
    }
}

// ============================================================================
// PERSISTENT fp16 logits GEMM, 512 threads:
// C[4096,32000] = (A/512)h @ Bh^T * 512 + bias.
// Tile map: tile t -> bm = (t % 32)*128, bn = (t / 32)*256.  16 chunks/tile.
// ============================================================================
__global__ void __launch_bounds__(NTHR, 1)
logits_persist(const __half* __restrict__ A, const __half* __restrict__ B,
               const float* __restrict__ bias, float* __restrict__ C,
               int ntiles, int gridsz)
{
    extern __shared__ char smem[];
    const uint32_t sb = smem_u32(smem);
    const int tid  = threadIdx.x;
    const int lane = tid & 31;
    const int warp = tid >> 5;
    const int wm   = (warp >> 3) * 64;
    const int wn   = (warp & 7) * 32;

    const int g = lane >> 3;
    const uint32_t frOff = (uint32_t)(((lane & 7) + (g & 1) * 8) * lh::PITCH + (g >> 1) * 16);

    if ((int)blockIdx.x >= ntiles) return;
    const int nt_mine = (ntiles - (int)blockIdx.x + gridsz - 1) / gridsz;
    const int NC = nt_mine * 16;

    float acc[4][4][4];
    #pragma unroll
    for (int mt = 0; mt < 4; mt++)
        #pragma unroll
        for (int nt = 0; nt < 4; nt++)
            #pragma unroll
            for (int r = 0; r < 4; r++) acc[mt][nt][r] = 0.f;

    auto load_chunk = [&](int cg) {
        const int tile = (int)blockIdx.x + (cg >> 4) * gridsz;
        const int bm = (tile & 31) << 7;
        const int bn = (tile >> 5) << 8;
        const int kb = (cg & 15) << 6;
        const __half* Ag = A + (size_t)bm * DM + kb;
        const __half* Bg = B + (size_t)bn * DM + kb;
        const uint32_t base = sb + (cg % 3) * lh::STG_BYTES;
        #pragma unroll
        for (int i = 0; i < 2; i++) {
            int idx = tid + i * NTHR;
            int row = idx >> 3, ch = idx & 7;
            cp16(base + row * lh::PITCH + ch * 16, Ag + (size_t)row * DM + ch * 8);
        }
        const uint32_t bb = base + lh::A_BYTES;
        #pragma unroll
        for (int i = 0; i < 4; i++) {
            int idx = tid + i * NTHR;
            int row = idx >> 3, ch = idx & 7;
            cp16(bb + row * lh::PITCH + ch * 16, Bg + (size_t)row * DM + ch * 8);
        }
        asm volatile("cp.async.commit_group;" ::: "memory");
    };

    load_chunk(0); load_chunk(1);   // NC >= 16, always valid

    for (int cg = 0; cg < NC; cg++) {
        // committed = cg + 2; wait_group 1 => completed >= cg+1 => stage cg ready
        asm volatile("cp.async.wait_group 1;" ::: "memory");
        __syncthreads();
        if (cg + 2 < NC) load_chunk(cg + 2);
        else asm volatile("cp.async.commit_group;" ::: "memory");

        const uint32_t sa  = sb + (cg % 3) * lh::STG_BYTES;
        const uint32_t sbb = sa + lh::A_BYTES;
        #pragma unroll
        for (int ks = 0; ks < 4; ks++) {
            uint32_t af[4][4], bf[4][2];
            #pragma unroll
            for (int mt = 0; mt < 4; mt++)
                ldsm4(af[mt], sa + (wm + mt * 16) * lh::PITCH + ks * 32 + frOff);
            #pragma unroll
            for (int p = 0; p < 2; p++) {
                uint32_t t4[4];
                ldsm4(t4, sbb + (wn + p * 16) * lh::PITCH + ks * 32 + frOff);
                bf[2 * p][0]     = t4[0]; bf[2 * p][1]     = t4[2];
                bf[2 * p + 1][0] = t4[1]; bf[2 * p + 1][1] = t4[3];
            }
            #pragma unroll
            for (int mt = 0; mt < 4; mt++)
                #pragma unroll
                for (int nt = 0; nt < 4; nt++)
                    mma16h(acc[mt][nt], af[mt], bf[nt]);
        }

        if ((cg & 15) == 15) {
            // tile finished: direct coalesced fragment stores (overlap next loads)
            const int tile = (int)blockIdx.x + (cg >> 4) * gridsz;
            const int bm = (tile & 31) << 7;
            const int bn = (tile >> 5) << 8;
            #pragma unroll
            for (int mt = 0; mt < 4; mt++) {
                #pragma unroll
                for (int nt = 0; nt < 4; nt++) {
                    int r = bm + wm + mt * 16 + (lane >> 2);
                    int c = bn + wn + nt * 8 + ((lane & 3) << 1);
                    const float2 bv = *(const float2*)(bias + c);
                    *(float2*)&C[(size_t)r * NVOCAB + c] = make_float2(
                        acc[mt][nt][0] * O_SCALE + bv.x,
                        acc[mt][nt][1] * O_SCALE + bv.y);
                    *(float2*)&C[(size_t)(r + 8) * NVOCAB + c] = make_float2(
                        acc[mt][nt][2] * O_SCALE + bv.x,
                        acc[mt][nt][3] * O_SCALE + bv.y);
                    acc[mt][nt][0] = 0.f; acc[mt][nt][1] = 0.f;
                    acc[mt][nt][2] = 0.f; acc[mt][nt][3] = 0.f;
                }
            }
        }
    }
}

// ============================================================================
// conversion / gather kernels
// ============================================================================
__global__ void __launch_bounds__(256)
cvt_f2h(const float* __restrict__ in, __half* __restrict__ out)
{
    size_t i = ((size_t)blockIdx.x * 256 + threadIdx.x) * 16;
    #pragma unroll
    for (int p = 0; p < 2; p++) {
        float4 v0 = *(const float4*)(in + i + p * 8);
        float4 v1 = *(const float4*)(in + i + p * 8 + 4);
        __half2 h[4];
        h[0] = __floats2half2_rn(v0.x, v0.y);
        h[1] = __floats2half2_rn(v0.z, v0.w);
        h[2] = __floats2half2_rn(v1.x, v1.y);
        h[3] = __floats2half2_rn(v1.z, v1.w);
        *(uint4*)(out + i + p * 8) = *(uint4*)h;
    }
}

// fused wq/wk/wv conversion: 3 x DM*DM fp32 -> [Wqk ; Wv]
__global__ void __launch_bounds__(256)
cvt_qkv(const float* __restrict__ wq, const float* __restrict__ wk,
        const float* __restrict__ wv, __half* __restrict__ wqk,
        __half* __restrict__ wvh)
{
    const int per = DM * DM / (256 * 16);   // blocks per matrix
    const int mat = blockIdx.x / per;
    const int blk = blockIdx.x % per;
    const float* in = (mat == 0) ? wq : (mat == 1) ? wk : wv;
    __half* out = (mat == 0) ? wqk : (mat == 1) ? (wqk + (size_t)DM * DM) : wvh;
    size_t i = ((size_t)blk * 256 + threadIdx.x) * 16;
    #pragma unroll
    for (int p = 0; p < 2; p++) {
        float4 v0 = *(const float4*)(in + i + p * 8);
        float4 v1 = *(const float4*)(in + i + p * 8 + 4);
        __half2 h[4];
        h[0] = __floats2half2_rn(v0.x, v0.y);
        h[1] = __floats2half2_rn(v0.z, v0.w);
        h[2] = __floats2half2_rn(v1.x, v1.y);
        h[3] = __floats2half2_rn(v1.z, v1.w);
        *(uint4*)(out + i + p * 8) = *(uint4*)h;
    }
}

__global__ void __launch_bounds__(256)
concat_bias(const float* __restrict__ bq, const float* __restrict__ bk,
            float* __restrict__ out)
{
    int i = blockIdx.x * 256 + threadIdx.x;
    out[i] = (i < DM) ? bq[i] : bk[i - DM];
}

__global__ void __launch_bounds__(256)
gather_cvt(const int* __restrict__ x, const float* __restrict__ emb,
           __half* __restrict__ out)
{
    const int t = blockIdx.x;
    const int d = threadIdx.x * 4;
    const float4 v = *(const float4*)(emb + (size_t)x[t] * DM + d);
    __half2 h0 = __floats2half2_rn(v.x, v.y);
    __half2 h1 = __floats2half2_rn(v.z, v.w);
    uint2 u;
    u.x = *(uint32_t*)&h0;
    u.y = *(uint32_t*)&h1;
    *(uint2*)(out + (size_t)t * DM + d) = u;
}

extern "C" void kernel_launch(void* const* d_in, const int* in_sizes, int n_in,
                              void* d_out, int out_size)
{
    (void)in_sizes; (void)n_in; (void)out_size;
    const int*   x   = (const int*)  d_in[0];
    const float* emb = (const float*)d_in[1];
    const float* wq  = (const float*)d_in[2];
    const float* bq  = (const float*)d_in[3];
    const float* wk  = (const float*)d_in[4];
    const float* bk  = (const float*)d_in[5];
    const float* wv  = (const float*)d_in[6];
    const float* bv  = (const float*)d_in[7];
    const float* wo  = (const float*)d_in[8];
    const float* bo  = (const float*)d_in[9];
    float* out = (float*)d_out;

    __half *eh, *QKh, *Vt, *Sh, *Oh, *Wh, *Wqk, *Wv;
    float* bqk;
    cudaGetSymbolAddress((void**)&eh,  g_eh);
    cudaGetSymbolAddress((void**)&QKh, g_QKh);
    cudaGetSymbolAddress((void**)&Vt,  g_Vt);
    cudaGetSymbolAddress((void**)&Sh,  g_Sh);
    cudaGetSymbolAddress((void**)&Oh,  g_Oh);
    cudaGetSymbolAddress((void**)&Wh,  g_Wh);
    cudaGetSymbolAddress((void**)&Wqk, g_Wqk);
    cudaGetSymbolAddress((void**)&Wv,  g_Wv);
    cudaGetSymbolAddress((void**)&bqk, g_bqk);

    int nsm = 148;
    cudaDeviceGetAttribute(&nsm, cudaDevAttrMultiProcessorCount, 0);

    cudaFuncSetAttribute(logits_persist,
                         cudaFuncAttributeMaxDynamicSharedMemorySize, lh::SMEM_TOT);
    cudaFuncSetAttribute(gemm_h<0, false>,
                         cudaFuncAttributeMaxDynamicSharedMemorySize, lh::SMEM_TOT);
    cudaFuncSetAttribute(gemm_h<5, false>,
                         cudaFuncAttributeMaxDynamicSharedMemorySize, lh::SMEM_TOT);
    cudaFuncSetAttribute(gemm_h<2, false>,
                         cudaFuncAttributeMaxDynamicSharedMemorySize, lh::SMEM_TOT);
    cudaFuncSetAttribute(gemm_h<6, true>,
                         cudaFuncAttributeMaxDynamicSharedMemorySize, lh::SMEM_TOT);

    dim3 thr(256), thrG(NTHR);

    // 0) conversions
    cvt_f2h<<<NVOCAB * DM / (256 * 16), thr>>>(wo, Wh);
    cvt_qkv<<<3 * DM * DM / (256 * 16), thr>>>(wq, wk, wv, Wqk, Wv);
    concat_bias<<<2 * DM / 256, thr>>>(bq, bk, bqk);
    gather_cvt<<<TOK, thr>>>(x, emb, eh);

    // 1) fused Q+K projection: QKh[4096,2048] = e_h @ Wqk^T, elu+1 + bias
    dim3 gQK(TOK / 128, 2 * DM / 256, 1);
    gemm_h<0, false><<<gQK, thrG, lh::SMEM_TOT>>>(eh, DM, Wqk, DM, bqk, QKh, 2 * DM, DM, 0, 0, 0);

    // 2) V pre-transposed: Vt[1024,4096] = wv @ e_h^T + bv (row bias)
    dim3 gVt(DM / 128, TOK / 256, 1);
    gemm_h<5, false><<<gVt, thrG, lh::SMEM_TOT>>>(Wv, DM, eh, DM, bv, Vt, TOK, DM, 0, 0, 0);

    // 3) causal scores per batch: S_b = tril(Q_b @ K_b^T), fp16
    dim3 gSc(SEQ / 128, SEQ / 256, NBATCH);
    gemm_h<2, false><<<gSc, thrG, lh::SMEM_TOT>>>(
        QKh, 2 * DM, QKh + DM, 2 * DM, nullptr, Sh, SEQ, DM,
        (long long)SEQ * 2 * DM, (long long)SEQ * 2 * DM, (long long)SEQ * SEQ);

    // 4) O_b = (S_b @ Vt_b^T) / 512, TRIK-truncated K loop
    dim3 gAV(SEQ / 128, DM / 256, NBATCH);
    gemm_h<6, true><<<gAV, thrG, lh::SMEM_TOT>>>(
        Sh, SEQ, Vt, TOK, nullptr, Oh, DM, SEQ,
        (long long)SEQ * SEQ, (long long)SEQ, (long long)SEQ * DM);

    // 5) logits (persistent): [4096,32000] = (Oh @ Wh^T) * 512 + bo
    const int ntiles = (TOK / 128) * (NVOCAB / 256);   // 4000
    logits_persist<<<nsm, thrG, lh::SMEM_TOT>>>(Oh, Wh, bo, out, ntiles, nsm);
}